// round 1
// baseline (speedup 1.0000x reference)
#include <cuda_runtime.h>
#include <cuda_bf16.h>
#include <cstdint>

// ---------------- problem constants ----------------
#define BB    4
#define TT    1024
#define CC    1024
#define HH    16
#define HD    64
#define LL    6
#define VV    16000
#define FF_   4096
#define TTXT  580
#define NPATCH 441
#define KIM   768      // 3*16*16
#define IMG   336
#define PATCH 16

// ---------------- scratch (device globals; no allocation) ----------------
__device__ float g_x [(size_t)BB*TT*CC];
__device__ float g_h [(size_t)BB*TT*CC];
__device__ float g_q [(size_t)BB*TT*CC];
__device__ float g_k [(size_t)BB*TT*CC];
__device__ float g_v [(size_t)BB*TT*CC];
__device__ float g_o [(size_t)BB*TT*CC];
__device__ float g_S [(size_t)BB*HH*TT*TT];      // 256MB attention scores
__device__ float g_ff[(size_t)BB*TT*FF_];
__device__ float g_im[(size_t)BB*NPATCH*KIM];
__device__ float g_p [(size_t)BB*NPATCH*CC];

// ---------------- generic fp32 tiled GEMM ----------------
// C[m,n] = alpha * sum_k A[m*asr + k] * B[k*bsk + n*bsn]  (+bias[n]) (+res) (relu)
// grid.z batching: z -> (zb = z/Hdiv, zh = z%Hdiv); offsets zb*xb1 + zh*xb2.
__global__ __launch_bounds__(256)
void gemm_f32(const float* __restrict__ A, const float* __restrict__ Bm,
              const float* __restrict__ bias, const float* __restrict__ res,
              float* __restrict__ Cm,
              int M, int N, int K,
              long long asr, long long bsk, long long bsn, long long csr,
              long long ab1, long long ab2, long long bb1, long long bb2,
              long long cb1, long long cb2, int Hdiv,
              float alpha, int relu)
{
    const int z  = blockIdx.z;
    const int zb = z / Hdiv, zh = z % Hdiv;
    A  += (long long)zb*ab1 + (long long)zh*ab2;
    Bm += (long long)zb*bb1 + (long long)zh*bb2;
    Cm += (long long)zb*cb1 + (long long)zh*cb2;
    if (res) res += (long long)zb*cb1 + (long long)zh*cb2;

    __shared__ float As[8][128];
    __shared__ float Bs[8][128];

    const int tid  = threadIdx.x;
    const int trow = (tid >> 4) << 3;   // 0..120
    const int tcol = (tid & 15) << 3;
    const int m0 = blockIdx.y * 128;
    const int n0 = blockIdx.x * 128;

    float acc[8][8];
    #pragma unroll
    for (int i = 0; i < 8; i++)
        #pragma unroll
        for (int j = 0; j < 8; j++) acc[i][j] = 0.f;

    const int arow = tid >> 1;
    const int akq  = (tid & 1) << 2;
    const int gmA  = m0 + arow;
    const bool aValid = (gmA < M);
    const float* Arow = A + (long long)gmA * asr + akq;

    for (int k0 = 0; k0 < K; k0 += 8) {
        float4 av = make_float4(0.f, 0.f, 0.f, 0.f);
        if (aValid) av = *(const float4*)(Arow + k0);
        As[akq+0][arow] = av.x; As[akq+1][arow] = av.y;
        As[akq+2][arow] = av.z; As[akq+3][arow] = av.w;

        #pragma unroll
        for (int i = 0; i < 4; i++) {
            int idx = tid + (i << 8);
            int kk  = idx >> 7;
            int nn  = idx & 127;
            int gn  = n0 + nn;
            float v = 0.f;
            if (gn < N) v = Bm[(long long)(k0 + kk) * bsk + (long long)gn * bsn];
            Bs[kk][nn] = v;
        }
        __syncthreads();

        #pragma unroll
        for (int kk = 0; kk < 8; kk++) {
            float4 a0 = *(const float4*)&As[kk][trow];
            float4 a1 = *(const float4*)&As[kk][trow + 4];
            float4 b0 = *(const float4*)&Bs[kk][tcol];
            float4 b1 = *(const float4*)&Bs[kk][tcol + 4];
            float a[8] = {a0.x,a0.y,a0.z,a0.w,a1.x,a1.y,a1.z,a1.w};
            float b[8] = {b0.x,b0.y,b0.z,b0.w,b1.x,b1.y,b1.z,b1.w};
            #pragma unroll
            for (int i = 0; i < 8; i++)
                #pragma unroll
                for (int j = 0; j < 8; j++)
                    acc[i][j] = fmaf(a[i], b[j], acc[i][j]);
        }
        __syncthreads();
    }

    #pragma unroll
    for (int i = 0; i < 8; i++) {
        int gm = m0 + trow + i;
        if (gm >= M) continue;
        #pragma unroll
        for (int j = 0; j < 8; j++) {
            int gn = n0 + tcol + j;
            if (gn >= N) continue;
            float v = acc[i][j] * alpha;
            if (bias) v += bias[gn];
            if (res)  v += res[(long long)gm * csr + gn];
            if (relu) v = fmaxf(v, 0.f);
            Cm[(long long)gm * csr + gn] = v;
        }
    }
}

// ---------------- block reductions ----------------
__device__ __forceinline__ float blockReduceSum256(float v, float* sh) {
    #pragma unroll
    for (int o = 16; o > 0; o >>= 1) v += __shfl_xor_sync(0xffffffffu, v, o);
    int w = threadIdx.x >> 5;
    if ((threadIdx.x & 31) == 0) sh[w] = v;
    __syncthreads();
    if (threadIdx.x < 8) {
        v = sh[threadIdx.x];
        #pragma unroll
        for (int o = 4; o > 0; o >>= 1) v += __shfl_xor_sync(0xffu, v, o);
        if (threadIdx.x == 0) sh[0] = v;
    }
    __syncthreads();
    float r = sh[0];
    __syncthreads();
    return r;
}

__device__ __forceinline__ float blockReduceMax256(float v, float* sh) {
    #pragma unroll
    for (int o = 16; o > 0; o >>= 1) v = fmaxf(v, __shfl_xor_sync(0xffffffffu, v, o));
    int w = threadIdx.x >> 5;
    if ((threadIdx.x & 31) == 0) sh[w] = v;
    __syncthreads();
    if (threadIdx.x < 8) {
        v = sh[threadIdx.x];
        #pragma unroll
        for (int o = 4; o > 0; o >>= 1) v = fmaxf(v, __shfl_xor_sync(0xffu, v, o));
        if (threadIdx.x == 0) sh[0] = v;
    }
    __syncthreads();
    float r = sh[0];
    __syncthreads();
    return r;
}

// ---------------- layernorm: one block per row, C=1024 ----------------
__global__ __launch_bounds__(256)
void layernorm_k(const float* __restrict__ x, const float* __restrict__ g,
                 const float* __restrict__ b, float* __restrict__ out)
{
    __shared__ float sh[8];
    const size_t row = blockIdx.x;
    const float* xr = x + row * CC;
    const int c = threadIdx.x * 4;
    float4 xv = *(const float4*)(xr + c);
    float s  = xv.x + xv.y + xv.z + xv.w;
    float ss = xv.x*xv.x + xv.y*xv.y + xv.z*xv.z + xv.w*xv.w;
    s  = blockReduceSum256(s,  sh);
    ss = blockReduceSum256(ss, sh);
    float mean = s * (1.f / CC);
    float var  = ss * (1.f / CC) - mean * mean;
    float inv  = rsqrtf(var + 1e-5f);
    float4 gv = *(const float4*)(g + c);
    float4 bv = *(const float4*)(b + c);
    float4 ov;
    ov.x = (xv.x - mean) * inv * gv.x + bv.x;
    ov.y = (xv.y - mean) * inv * gv.y + bv.y;
    ov.z = (xv.z - mean) * inv * gv.z + bv.z;
    ov.w = (xv.w - mean) * inv * gv.w + bv.w;
    *(float4*)(out + row * CC + c) = ov;
}

// ---------------- causal softmax: one block per (b,h,i) row ----------------
__global__ __launch_bounds__(256)
void softmax_causal_k(float* __restrict__ S)
{
    __shared__ float sh[8];
    const int r = blockIdx.x;          // (b*H+h)*T + i
    const int i = r & (TT - 1);
    float* row = S + (size_t)r * TT;
    const int tid = threadIdx.x;
    float vals[4];
    float mx = -1e30f;
    #pragma unroll
    for (int u = 0; u < 4; u++) {
        int j = tid + (u << 8);
        vals[u] = (j <= i) ? row[j] : -1e30f;
        mx = fmaxf(mx, vals[u]);
    }
    mx = blockReduceMax256(mx, sh);
    float sum = 0.f;
    #pragma unroll
    for (int u = 0; u < 4; u++) {
        int j = tid + (u << 8);
        float e = (j <= i) ? __expf(vals[u] - mx) : 0.f;
        vals[u] = e;
        sum += e;
    }
    sum = blockReduceSum256(sum, sh);
    float invs = 1.f / sum;
    #pragma unroll
    for (int u = 0; u < 4; u++) {
        int j = tid + (u << 8);
        row[j] = vals[u] * invs;
    }
}

// ---------------- im2col for patch conv ----------------
__global__ void im2col_k(const float* __restrict__ img, float* __restrict__ out)
{
    int idx = blockIdx.x * 256 + threadIdx.x;
    if (idx >= BB * NPATCH * KIM) return;
    int k  = idx % KIM;
    int bn = idx / KIM;
    int n  = bn % NPATCH;
    int b  = bn / NPATCH;
    int ci = k >> 8;            // /256
    int rr = k & 255;
    int kh = rr >> 4;
    int kw = rr & 15;
    int ph = n / 21, pw = n % 21;
    out[idx] = img[(((size_t)b * 3 + ci) * IMG + ph * PATCH + kh) * IMG + pw * PATCH + kw];
}

// ---------------- embedding assembly ----------------
__global__ __launch_bounds__(256)
void embed_k(const int* __restrict__ toks, const float* __restrict__ tok_emb,
             const float* __restrict__ txt_pos, const float* __restrict__ img_pos,
             const float* __restrict__ p, float* __restrict__ x)
{
    const int bt = blockIdx.x;
    const int b  = bt >> 10;
    const int t  = bt & 1023;
    const int c  = threadIdx.x * 4;
    const float* src;
    const float* extra = nullptr;
    if (t == 0)        src = tok_emb + 1 * CC;        // BOS
    else if (t == 1)   src = tok_emb + 8 * CC;        // IMG_START
    else if (t < 443) {
        int n = t - 2;
        src = p + ((size_t)(b * NPATCH + n)) * CC;
        extra = img_pos + (size_t)n * CC;
    }
    else if (t == 443) src = tok_emb + 9 * CC;        // IMG_END
    else {
        int tok = toks[b * TTXT + (t - 444)];
        src = tok_emb + (size_t)tok * CC;
    }
    float4 v  = *(const float4*)(src + c);
    float4 tp = *(const float4*)(txt_pos + (size_t)t * CC + c);
    v.x += tp.x; v.y += tp.y; v.z += tp.z; v.w += tp.w;
    if (extra) {
        float4 e = *(const float4*)(extra + c);
        v.x += e.x; v.y += e.y; v.z += e.z; v.w += e.w;
    }
    *(float4*)(x + (size_t)bt * CC + c) = v;
}

// ---------------- host-side launcher ----------------
static inline void launch_gemm(const float* A, const float* B, const float* bias,
                               const float* res, float* C,
                               int M, int N, int K,
                               long long asr, long long bsk, long long bsn, long long csr,
                               float alpha = 1.f, int relu = 0,
                               int nz = 1, int Hdiv = 1,
                               long long ab1 = 0, long long ab2 = 0,
                               long long bb1 = 0, long long bb2 = 0,
                               long long cb1 = 0, long long cb2 = 0)
{
    dim3 grid((N + 127) / 128, (M + 127) / 128, nz);
    gemm_f32<<<grid, 256>>>(A, B, bias, res, C, M, N, K,
                            asr, bsk, bsn, csr,
                            ab1, ab2, bb1, bb2, cb1, cb2, Hdiv, alpha, relu);
}

extern "C" void kernel_launch(void* const* d_in, const int* in_sizes, int n_in,
                              void* d_out, int out_size)
{
    const int*   text_tokens = (const int*)  d_in[0];
    const float* images      = (const float*)d_in[1];
    const float* tok_emb     = (const float*)d_in[2];
    const float* txt_pos     = (const float*)d_in[3];
    const float* img_pos     = (const float*)d_in[4];
    const float* patch_w     = (const float*)d_in[5];
    const float* patch_b     = (const float*)d_in[6];
    const float* ln1_g       = (const float*)d_in[7];
    const float* ln1_b       = (const float*)d_in[8];
    const float* wq          = (const float*)d_in[9];
    const float* wk          = (const float*)d_in[10];
    const float* wv          = (const float*)d_in[11];
    const float* wo          = (const float*)d_in[12];
    const float* bo          = (const float*)d_in[13];
    const float* ln2_g       = (const float*)d_in[14];
    const float* ln2_b       = (const float*)d_in[15];
    const float* w1          = (const float*)d_in[16];
    const float* b1          = (const float*)d_in[17];
    const float* w2          = (const float*)d_in[18];
    const float* b2          = (const float*)d_in[19];
    const float* lnf_g       = (const float*)d_in[20];
    const float* lnf_b       = (const float*)d_in[21];
    const float* lm_w        = (const float*)d_in[22];
    const float* lm_b        = (const float*)d_in[23];
    float* out = (float*)d_out;

    float *px, *ph, *pq, *pk, *pv, *po, *pS, *pff, *pim, *pp;
    cudaGetSymbolAddress((void**)&px,  g_x);
    cudaGetSymbolAddress((void**)&ph,  g_h);
    cudaGetSymbolAddress((void**)&pq,  g_q);
    cudaGetSymbolAddress((void**)&pk,  g_k);
    cudaGetSymbolAddress((void**)&pv,  g_v);
    cudaGetSymbolAddress((void**)&po,  g_o);
    cudaGetSymbolAddress((void**)&pS,  g_S);
    cudaGetSymbolAddress((void**)&pff, g_ff);
    cudaGetSymbolAddress((void**)&pim, g_im);
    cudaGetSymbolAddress((void**)&pp,  g_p);

    const int M  = BB * TT;          // 4096
    const float scale = 0.125f;      // HD^-0.5

    // 1) patch embedding: im2col + GEMM (A[1764,768] @ patch_w^T[768,1024] + patch_b)
    {
        int tot = BB * NPATCH * KIM;
        im2col_k<<<(tot + 255) / 256, 256>>>(images, pim);
        launch_gemm(pim, patch_w, patch_b, nullptr, pp,
                    BB * NPATCH, CC, KIM,
                    KIM, 1, KIM, CC);
    }

    // 2) embedding assembly -> g_x
    embed_k<<<BB * TT, 256>>>(text_tokens, tok_emb, txt_pos, img_pos, pp, px);

    // 3) transformer blocks
    for (int l = 0; l < LL; l++) {
        const float* Wq = wq + (size_t)l * CC * CC;
        const float* Wk = wk + (size_t)l * CC * CC;
        const float* Wv = wv + (size_t)l * CC * CC;
        const float* Wo = wo + (size_t)l * CC * CC;
        const float* Bo = bo + (size_t)l * CC;
        const float* W1 = w1 + (size_t)l * CC * FF_;
        const float* B1 = b1 + (size_t)l * FF_;
        const float* W2 = w2 + (size_t)l * FF_ * CC;
        const float* B2 = b2 + (size_t)l * CC;

        // ln1
        layernorm_k<<<M, 256>>>(px, ln1_g + l * CC, ln1_b + l * CC, ph);

        // q, k, v projections (no bias)
        launch_gemm(ph, Wq, nullptr, nullptr, pq, M, CC, CC, CC, CC, 1, CC);
        launch_gemm(ph, Wk, nullptr, nullptr, pk, M, CC, CC, CC, CC, 1, CC);
        launch_gemm(ph, Wv, nullptr, nullptr, pv, M, CC, CC, CC, CC, 1, CC);

        // scores: S[b,h,i,j] = scale * q[b,i,h,:] . k[b,j,h,:]   (batched over b,h)
        launch_gemm(pq, pk, nullptr, nullptr, pS,
                    TT, TT, HD,
                    /*asr*/ CC, /*bsk*/ 1, /*bsn*/ CC, /*csr*/ TT,
                    scale, 0,
                    BB * HH, HH,
                    /*ab1*/ (long long)TT * CC, /*ab2*/ HD,
                    /*bb1*/ (long long)TT * CC, /*bb2*/ HD,
                    /*cb1*/ (long long)HH * TT * TT, /*cb2*/ (long long)TT * TT);

        // causal softmax
        softmax_causal_k<<<BB * HH * TT, 256>>>(pS);

        // attn out: O[b,i,h,d] = sum_j A[b,h,i,j] * v[b,j,h,d]
        launch_gemm(pS, pv, nullptr, nullptr, po,
                    TT, HD, TT,
                    /*asr*/ TT, /*bsk*/ CC, /*bsn*/ 1, /*csr*/ CC,
                    1.f, 0,
                    BB * HH, HH,
                    /*ab1*/ (long long)HH * TT * TT, /*ab2*/ (long long)TT * TT,
                    /*bb1*/ (long long)TT * CC, /*bb2*/ HD,
                    /*cb1*/ (long long)TT * CC, /*cb2*/ HD);

        // output projection + bias + residual -> x
        launch_gemm(po, Wo, Bo, px, px, M, CC, CC, CC, CC, 1, CC);

        // ln2
        layernorm_k<<<M, 256>>>(px, ln2_g + l * CC, ln2_b + l * CC, ph);

        // ffn
        launch_gemm(ph, W1, B1, nullptr, pff, M, FF_, CC, CC, FF_, 1, FF_, 1.f, /*relu*/1);
        launch_gemm(pff, W2, B2, px, px, M, CC, FF_, FF_, CC, 1, CC);
    }

    // 4) final LN + LM head
    layernorm_k<<<M, 256>>>(px, lnf_g, lnf_b, ph);
    launch_gemm(ph, lm_w, lm_b, nullptr, out, M, VV, CC, CC, VV, 1, VV);
}

// round 3
// speedup vs baseline: 2.6816x; 2.6816x over previous
#include <cuda_runtime.h>
#include <cuda_bf16.h>
#include <cstdint>

typedef __nv_bfloat16 bf16;

// ---------------- problem constants ----------------
#define BB    4
#define TT    1024
#define CC    1024
#define HH    16
#define HD    64
#define LL    6
#define VV    16000
#define FF_   4096
#define TTXT  580
#define NPATCH 441
#define KIM   768
#define IMG   336
#define PATCH 16
#define MTOK  (BB*TT)          // 4096

// ---------------- scratch (device globals; no allocation) ----------------
__device__ float g_x [(size_t)MTOK*CC];
__device__ float g_q [(size_t)MTOK*CC];
__device__ float g_k [(size_t)MTOK*CC];
__device__ float g_v [(size_t)MTOK*CC];
__device__ float g_S [(size_t)BB*HH*TT*TT];
__device__ float g_pp[(size_t)BB*NPATCH*CC];

__device__ bf16 g_Sh[(size_t)BB*HH*TT*TT];
__device__ bf16 g_Sl[(size_t)BB*HH*TT*TT];
__device__ bf16 g_qh[(size_t)MTOK*CC], g_ql[(size_t)MTOK*CC];
__device__ bf16 g_kh[(size_t)MTOK*CC], g_kl[(size_t)MTOK*CC];
__device__ bf16 g_vth[(size_t)MTOK*CC], g_vtl[(size_t)MTOK*CC];
__device__ bf16 g_ah[(size_t)MTOK*CC], g_al[(size_t)MTOK*CC];
__device__ bf16 g_fh[(size_t)MTOK*FF_], g_fl[(size_t)MTOK*FF_];

__device__ bf16 g_wqh[(size_t)LL*CC*CC], g_wql[(size_t)LL*CC*CC];
__device__ bf16 g_wkh[(size_t)LL*CC*CC], g_wkl[(size_t)LL*CC*CC];
__device__ bf16 g_wvh[(size_t)LL*CC*CC], g_wvl[(size_t)LL*CC*CC];
__device__ bf16 g_woh[(size_t)LL*CC*CC], g_wol[(size_t)LL*CC*CC];
__device__ bf16 g_w1h[(size_t)LL*CC*FF_], g_w1l[(size_t)LL*CC*FF_];
__device__ bf16 g_w2h[(size_t)LL*CC*FF_], g_w2l[(size_t)LL*CC*FF_];
__device__ bf16 g_lmh[(size_t)CC*VV],    g_lml[(size_t)CC*VV];
__device__ bf16 g_pwh[(size_t)CC*KIM],   g_pwl[(size_t)CC*KIM];
__device__ bf16 g_imh[(size_t)BB*NPATCH*KIM], g_iml[(size_t)BB*NPATCH*KIM];

// ---------------- low-level helpers ----------------
__device__ __forceinline__ uint32_t smem_u32(const void* p) {
    uint32_t a;
    asm("{ .reg .u64 t; cvta.to.shared.u64 t, %1; cvt.u32.u64 %0, t; }" : "=r"(a) : "l"(p));
    return a;
}
__device__ __forceinline__ void cpa16(uint32_t dst, const void* src, int szbytes) {
    asm volatile("cp.async.cg.shared.global [%0], [%1], 16, %2;"
                 :: "r"(dst), "l"(src), "r"(szbytes) : "memory");
}
__device__ __forceinline__ void ldsm4(uint32_t (&r)[4], uint32_t addr) {
    asm volatile("ldmatrix.sync.aligned.m8n8.x4.shared.b16 {%0,%1,%2,%3}, [%4];"
                 : "=r"(r[0]), "=r"(r[1]), "=r"(r[2]), "=r"(r[3]) : "r"(addr));
}
__device__ __forceinline__ void mma_bf16(float (&d)[4], const uint32_t (&a)[4],
                                         uint32_t b0, uint32_t b1) {
    asm volatile("mma.sync.aligned.m16n8k16.row.col.f32.bf16.bf16.f32 "
                 "{%0,%1,%2,%3}, {%4,%5,%6,%7}, {%8,%9}, {%0,%1,%2,%3};"
                 : "+f"(d[0]), "+f"(d[1]), "+f"(d[2]), "+f"(d[3])
                 : "r"(a[0]), "r"(a[1]), "r"(a[2]), "r"(a[3]), "r"(b0), "r"(b1));
}

// ---------------- split-bf16 tensor-core GEMM (mma.sync) ----------------
// C = alpha * (Ah+Al)[M,K] @ (Bh+Bl)[N,K]^T  (+bias/res/relu); A,B row-major [*,K]
#define KC  32
#define LDS 40
#define BM  128

template<int BN, int WROWS, int WCOLS>
__global__ __launch_bounds__(256)
void gemm_mma(const bf16* __restrict__ Ah, const bf16* __restrict__ Al,
              const bf16* __restrict__ Bh, const bf16* __restrict__ Bl,
              const float* __restrict__ bias, const float* __restrict__ res,
              float* __restrict__ outF, bf16* __restrict__ outH, bf16* __restrict__ outL,
              int M, int Nfull, int K, int ldc,
              long long ab1, long long ab2, long long bb1, long long bb2,
              long long cb1, long long cb2, int Hdiv,
              float alpha, int relu, int kLimit, int tri)
{
    constexpr int WM = BM / WROWS;       // rows per warp
    constexpr int WN = BN / WCOLS;       // cols per warp
    constexpr int MI = WM / 16;
    constexpr int NI = WN / 8;
    constexpr int ASZ = BM * LDS;        // elems per A matrix per stage
    constexpr int BSZ = BN * LDS;

    const int m0 = blockIdx.y * BM;
    const int n0 = blockIdx.x * BN;
    if (tri && n0 > m0 + (BM - 1)) return;

    const int z = blockIdx.z, zb = z / Hdiv, zh = z % Hdiv;
    Ah += (long long)zb*ab1 + (long long)zh*ab2;
    Al += (long long)zb*ab1 + (long long)zh*ab2;
    Bh += (long long)zb*bb1 + (long long)zh*bb2;
    Bl += (long long)zb*bb1 + (long long)zh*bb2;
    const long long coff = (long long)zb*cb1 + (long long)zh*cb2;

    extern __shared__ bf16 sm[];
    const uint32_t sbase = smem_u32(sm);

    const int tid = threadIdx.x;
    int Keff = K;
    if (kLimit) { int kl = m0 + BM; if (kl < Keff) Keff = kl; }
    const int nch = Keff >> 5;

    auto load_stage = [&](int st, int k0) {
        #pragma unroll
        for (int i = tid; i < BM * 4; i += 256) {
            int r = i >> 2, c8 = (i & 3) << 3;
            int gr = m0 + r;
            int ok = (gr < M) ? 16 : 0;
            if (gr >= M) gr = m0;
            size_t go = (size_t)gr * K + k0 + c8;
            uint32_t so = (uint32_t)((st * ASZ + r * LDS + c8) * 2);
            cpa16(sbase + so, Ah + go, ok);
            cpa16(sbase + so + 2 * ASZ * 2, Al + go, ok);
        }
        #pragma unroll
        for (int i = tid; i < BN * 4; i += 256) {
            int r = i >> 2, c8 = (i & 3) << 3;
            int gn = n0 + r;
            int ok = (gn < Nfull) ? 16 : 0;
            if (gn >= Nfull) gn = n0;
            size_t go = (size_t)gn * K + k0 + c8;
            uint32_t so = (uint32_t)((4 * ASZ + st * BSZ + r * LDS + c8) * 2);
            cpa16(sbase + so, Bh + go, ok);
            cpa16(sbase + so + 2 * BSZ * 2, Bl + go, ok);
        }
        asm volatile("cp.async.commit_group;" ::: "memory");
    };

    const int wid = tid >> 5, lane = tid & 31;
    const int wr = wid % WROWS, wc = wid / WROWS;
    const int wmBase = wr * WM, wnBase = wc * WN;

    float acc[MI][NI][4];
    #pragma unroll
    for (int mi = 0; mi < MI; mi++)
        #pragma unroll
        for (int ni = 0; ni < NI; ni++)
            #pragma unroll
            for (int j = 0; j < 4; j++) acc[mi][ni][j] = 0.f;

    load_stage(0, 0);

    for (int ch = 0; ch < nch; ch++) {
        if (ch + 1 < nch) {
            load_stage((ch + 1) & 1, (ch + 1) << 5);
            asm volatile("cp.async.wait_group 1;" ::: "memory");
        } else {
            asm volatile("cp.async.wait_group 0;" ::: "memory");
        }
        __syncthreads();

        const int st = ch & 1;
        const uint32_t aHb = sbase + (uint32_t)(st * ASZ * 2);
        const uint32_t aLb = aHb + (uint32_t)(2 * ASZ * 2);
        const uint32_t bHb = sbase + (uint32_t)((4 * ASZ + st * BSZ) * 2);
        const uint32_t bLb = bHb + (uint32_t)(2 * BSZ * 2);

        #pragma unroll
        for (int kk = 0; kk < 2; kk++) {
            const int colOff = kk * 16 + ((lane >> 4) << 3);
            uint32_t afH[MI][4], afL[MI][4];
            #pragma unroll
            for (int mi = 0; mi < MI; mi++) {
                uint32_t off = (uint32_t)(((wmBase + mi * 16 + (lane & 15)) * LDS + colOff) * 2);
                ldsm4(afH[mi], aHb + off);
                ldsm4(afL[mi], aLb + off);
            }
            #pragma unroll
            for (int nj = 0; nj < NI / 2; nj++) {
                uint32_t off = (uint32_t)(((wnBase + nj * 16 + (lane & 15)) * LDS + colOff) * 2);
                uint32_t bfH[4], bfL[4];
                ldsm4(bfH, bHb + off);
                ldsm4(bfL, bLb + off);
                #pragma unroll
                for (int mi = 0; mi < MI; mi++) {
                    mma_bf16(acc[mi][2*nj],   afH[mi], bfH[0], bfH[2]);
                    mma_bf16(acc[mi][2*nj],   afH[mi], bfL[0], bfL[2]);
                    mma_bf16(acc[mi][2*nj],   afL[mi], bfH[0], bfH[2]);
                    mma_bf16(acc[mi][2*nj+1], afH[mi], bfH[1], bfH[3]);
                    mma_bf16(acc[mi][2*nj+1], afH[mi], bfL[1], bfL[3]);
                    mma_bf16(acc[mi][2*nj+1], afL[mi], bfH[1], bfH[3]);
                }
            }
        }
        __syncthreads();
    }

    // epilogue
    const int g = lane >> 2, t4 = lane & 3;
    #pragma unroll
    for (int mi = 0; mi < MI; mi++) {
        #pragma unroll
        for (int ni = 0; ni < NI; ni++) {
            int col = n0 + wnBase + ni * 8 + t4 * 2;
            if (col >= Nfull) continue;
            #pragma unroll
            for (int half = 0; half < 2; half++) {
                int row = m0 + wmBase + mi * 16 + g + half * 8;
                if (row >= M) continue;
                float v0 = acc[mi][ni][half * 2 + 0] * alpha;
                float v1 = acc[mi][ni][half * 2 + 1] * alpha;
                long long base = coff + (long long)row * ldc + col;
                if (bias) { v0 += bias[col]; v1 += bias[col + 1]; }
                if (res)  { v0 += res[base]; v1 += res[base + 1]; }
                if (relu) { v0 = fmaxf(v0, 0.f); v1 = fmaxf(v1, 0.f); }
                if (outF) *(float2*)(outF + base) = make_float2(v0, v1);
                if (outH) {
                    bf16 h0 = __float2bfloat16(v0), h1 = __float2bfloat16(v1);
                    float r0 = v0 - __bfloat162float(h0), r1 = v1 - __bfloat162float(h1);
                    bf16 l0 = __float2bfloat16(r0), l1 = __float2bfloat16(r1);
                    uint32_t hw = (uint32_t)__bfloat16_as_ushort(h0) |
                                  ((uint32_t)__bfloat16_as_ushort(h1) << 16);
                    uint32_t lw = (uint32_t)__bfloat16_as_ushort(l0) |
                                  ((uint32_t)__bfloat16_as_ushort(l1) << 16);
                    *(uint32_t*)(outH + base) = hw;
                    *(uint32_t*)(outL + base) = lw;
                }
            }
        }
    }
}

// ---------------- block reductions ----------------
__device__ __forceinline__ float blockReduceSum256(float v, float* sh) {
    #pragma unroll
    for (int o = 16; o > 0; o >>= 1) v += __shfl_xor_sync(0xffffffffu, v, o);
    int w = threadIdx.x >> 5;
    if ((threadIdx.x & 31) == 0) sh[w] = v;
    __syncthreads();
    if (threadIdx.x < 8) {
        v = sh[threadIdx.x];
        #pragma unroll
        for (int o = 4; o > 0; o >>= 1) v += __shfl_xor_sync(0xffu, v, o);
        if (threadIdx.x == 0) sh[0] = v;
    }
    __syncthreads();
    float r = sh[0]; __syncthreads(); return r;
}
__device__ __forceinline__ float blockReduceMax256(float v, float* sh) {
    #pragma unroll
    for (int o = 16; o > 0; o >>= 1) v = fmaxf(v, __shfl_xor_sync(0xffffffffu, v, o));
    int w = threadIdx.x >> 5;
    if ((threadIdx.x & 31) == 0) sh[w] = v;
    __syncthreads();
    if (threadIdx.x < 8) {
        v = sh[threadIdx.x];
        #pragma unroll
        for (int o = 4; o > 0; o >>= 1) v = fmaxf(v, __shfl_xor_sync(0xffu, v, o));
        if (threadIdx.x == 0) sh[0] = v;
    }
    __syncthreads();
    float r = sh[0]; __syncthreads(); return r;
}

__device__ __forceinline__ void split_store(bf16* H, bf16* L, size_t i, float v) {
    bf16 h = __float2bfloat16(v);
    H[i] = h;
    L[i] = __float2bfloat16(v - __bfloat162float(h));
}

// ---------------- layernorm -> split bf16 ----------------
__global__ __launch_bounds__(256)
void layernorm_split_k(const float* __restrict__ x, const float* __restrict__ g,
                       const float* __restrict__ b, bf16* __restrict__ oh, bf16* __restrict__ ol)
{
    __shared__ float sh[8];
    const size_t row = blockIdx.x;
    const float* xr = x + row * CC;
    const int c = threadIdx.x * 4;
    float4 xv = *(const float4*)(xr + c);
    float s  = xv.x + xv.y + xv.z + xv.w;
    float ss = xv.x*xv.x + xv.y*xv.y + xv.z*xv.z + xv.w*xv.w;
    s = blockReduceSum256(s, sh);
    ss = blockReduceSum256(ss, sh);
    float mean = s * (1.f / CC);
    float var = ss * (1.f / CC) - mean * mean;
    float inv = rsqrtf(var + 1e-5f);
    float4 gv = *(const float4*)(g + c);
    float4 bv = *(const float4*)(b + c);
    size_t base = row * CC + c;
    split_store(oh, ol, base + 0, (xv.x - mean) * inv * gv.x + bv.x);
    split_store(oh, ol, base + 1, (xv.y - mean) * inv * gv.y + bv.y);
    split_store(oh, ol, base + 2, (xv.z - mean) * inv * gv.z + bv.z);
    split_store(oh, ol, base + 3, (xv.w - mean) * inv * gv.w + bv.w);
}

// ---------------- causal softmax -> split bf16 ----------------
__global__ __launch_bounds__(256)
void softmax_split_k(const float* __restrict__ S, bf16* __restrict__ Ph, bf16* __restrict__ Pl)
{
    __shared__ float sh[8];
    const int r = blockIdx.x;
    const int i = r & (TT - 1);
    const float* row = S + (size_t)r * TT;
    const int tid = threadIdx.x;
    float vals[4];
    float mx = -1e30f;
    #pragma unroll
    for (int u = 0; u < 4; u++) {
        int j = tid + (u << 8);
        vals[u] = (j <= i) ? row[j] : -1e30f;
        mx = fmaxf(mx, vals[u]);
    }
    mx = blockReduceMax256(mx, sh);
    float sum = 0.f;
    #pragma unroll
    for (int u = 0; u < 4; u++) {
        int j = tid + (u << 8);
        float e = (j <= i) ? __expf(vals[u] - mx) : 0.f;
        vals[u] = e; sum += e;
    }
    sum = blockReduceSum256(sum, sh);
    float invs = 1.f / sum;
    #pragma unroll
    for (int u = 0; u < 4; u++) {
        int j = tid + (u << 8);
        split_store(Ph, Pl, (size_t)r * TT + j, vals[u] * invs);
    }
}

// ---------------- repack q,k -> [B,H,T,HD] split; v -> [B,H,HD,T] split ----------------
__global__ __launch_bounds__(256)
void repack_qkv_k(const float* __restrict__ q, const float* __restrict__ k, const float* __restrict__ v,
                  bf16* qh, bf16* ql, bf16* kh, bf16* kl, bf16* vth, bf16* vtl)
{
    size_t idx = (size_t)blockIdx.x * 256 + threadIdx.x;
    int c = idx & 1023;
    size_t bt = idx >> 10;
    int t = bt & 1023;
    int b = bt >> 10;
    int h = c >> 6, d = c & 63;
    size_t o1 = (((size_t)(b * HH + h)) * TT + t) * HD + d;
    split_store(qh, ql, o1, q[idx]);
    split_store(kh, kl, o1, k[idx]);
    size_t o2 = (((size_t)(b * HH + h)) * HD + d) * TT + t;
    split_store(vth, vtl, o2, v[idx]);
}

// ---------------- weight transpose + split: W[K,N] -> Wt[N,K] hi/lo ----------------
__global__ void transpose_split_k(const float* __restrict__ W, bf16* __restrict__ hi,
                                  bf16* __restrict__ lo, int K, int N)
{
    __shared__ float t[32][33];
    const size_t zo = (size_t)blockIdx.z * K * N;
    W += zo; hi += zo; lo += zo;
    int k0 = blockIdx.y * 32, n0 = blockIdx.x * 32;
    int tx = threadIdx.x, ty = threadIdx.y;
    #pragma unroll
    for (int i = 0; i < 32; i += 8)
        t[ty + i][tx] = W[(size_t)(k0 + ty + i) * N + n0 + tx];
    __syncthreads();
    #pragma unroll
    for (int i = 0; i < 32; i += 8)
        split_store(hi, lo, (size_t)(n0 + ty + i) * K + k0 + tx, t[tx][ty + i]);
}

// ---------------- elementwise split ----------------
__global__ void split_k(const float* __restrict__ W, bf16* hi, bf16* lo, int n)
{
    int idx = blockIdx.x * 256 + threadIdx.x;
    if (idx < n) split_store(hi, lo, idx, W[idx]);
}

// ---------------- im2col + split ----------------
__global__ void im2col_split_k(const float* __restrict__ img, bf16* hi, bf16* lo)
{
    int idx = blockIdx.x * 256 + threadIdx.x;
    if (idx >= BB * NPATCH * KIM) return;
    int k = idx % KIM;
    int bn = idx / KIM;
    int n = bn % NPATCH;
    int b = bn / NPATCH;
    int ci = k >> 8;
    int rr = k & 255;
    int kh = rr >> 4;
    int kw = rr & 15;
    int ph = n / 21, pw = n % 21;
    float v = img[(((size_t)b * 3 + ci) * IMG + ph * PATCH + kh) * IMG + pw * PATCH + kw];
    split_store(hi, lo, idx, v);
}

// ---------------- embedding assembly ----------------
__global__ __launch_bounds__(256)
void embed_k(const int* __restrict__ toks, const float* __restrict__ tok_emb,
             const float* __restrict__ txt_pos, const float* __restrict__ img_pos,
             const float* __restrict__ p, float* __restrict__ x)
{
    const int bt = blockIdx.x;
    const int b = bt >> 10;
    const int t = bt & 1023;
    const int c = threadIdx.x * 4;
    const float* src;
    const float* extra = nullptr;
    if (t == 0)      src = tok_emb + 1 * CC;
    else if (t == 1) src = tok_emb + 8 * CC;
    else if (t < 443) {
        int n = t - 2;
        src = p + ((size_t)(b * NPATCH + n)) * CC;
        extra = img_pos + (size_t)n * CC;
    }
    else if (t == 443) src = tok_emb + 9 * CC;
    else {
        int tok = toks[b * TTXT + (t - 444)];
        src = tok_emb + (size_t)tok * CC;
    }
    float4 v = *(const float4*)(src + c);
    float4 tp = *(const float4*)(txt_pos + (size_t)t * CC + c);
    v.x += tp.x; v.y += tp.y; v.z += tp.z; v.w += tp.w;
    if (extra) {
        float4 e = *(const float4*)(extra + c);
        v.x += e.x; v.y += e.y; v.z += e.z; v.w += e.w;
    }
    *(float4*)(x + (size_t)bt * CC + c) = v;
}

// ---------------- host-side GEMM launcher ----------------
static inline void tc(const bf16* Ah, const bf16* Al, const bf16* Bh, const bf16* Bl,
                      const float* bias, const float* res,
                      float* outF, bf16* outH, bf16* outL,
                      int M, int N, int K, int ldc, int Ntile,
                      float alpha = 1.f, int relu = 0, int kLimit = 0, int tri = 0,
                      int nz = 1, int Hdiv = 1,
                      long long ab1 = 0, long long ab2 = 0,
                      long long bb1 = 0, long long bb2 = 0,
                      long long cb1 = 0, long long cb2 = 0)
{
    dim3 grid((N + Ntile - 1) / Ntile, (M + 127) / 128, nz);
    if (Ntile == 64) {
        size_t sh = (size_t)(4 * 128 * LDS + 4 * 64 * LDS) * 2;
        gemm_mma<64, 8, 1><<<grid, 256, sh>>>(Ah, Al, Bh, Bl, bias, res, outF, outH, outL,
            M, N, K, ldc, ab1, ab2, bb1, bb2, cb1, cb2, Hdiv, alpha, relu, kLimit, tri);
    } else {
        size_t sh = (size_t)(4 * 128 * LDS + 4 * 128 * LDS) * 2;
        gemm_mma<128, 4, 2><<<grid, 256, sh>>>(Ah, Al, Bh, Bl, bias, res, outF, outH, outL,
            M, N, K, ldc, ab1, ab2, bb1, bb2, cb1, cb2, Hdiv, alpha, relu, kLimit, tri);
    }
}

#define SYM(name) ({ void* _p; cudaGetSymbolAddress(&_p, name); _p; })

extern "C" void kernel_launch(void* const* d_in, const int* in_sizes, int n_in,
                              void* d_out, int out_size)
{
    const int*   text_tokens = (const int*)  d_in[0];
    const float* images      = (const float*)d_in[1];
    const float* tok_emb     = (const float*)d_in[2];
    const float* txt_pos     = (const float*)d_in[3];
    const float* img_pos     = (const float*)d_in[4];
    const float* patch_w     = (const float*)d_in[5];
    const float* patch_b     = (const float*)d_in[6];
    const float* ln1_g       = (const float*)d_in[7];
    const float* ln1_b       = (const float*)d_in[8];
    const float* wq          = (const float*)d_in[9];
    const float* wk          = (const float*)d_in[10];
    const float* wv          = (const float*)d_in[11];
    const float* wo          = (const float*)d_in[12];
    const float* bo          = (const float*)d_in[13];
    const float* ln2_g       = (const float*)d_in[14];
    const float* ln2_b       = (const float*)d_in[15];
    const float* w1          = (const float*)d_in[16];
    const float* b1          = (const float*)d_in[17];
    const float* w2          = (const float*)d_in[18];
    const float* b2          = (const float*)d_in[19];
    const float* lnf_g       = (const float*)d_in[20];
    const float* lnf_b       = (const float*)d_in[21];
    const float* lm_w        = (const float*)d_in[22];
    const float* lm_b        = (const float*)d_in[23];
    float* out = (float*)d_out;

    cudaFuncSetAttribute(gemm_mma<128, 4, 2>, cudaFuncAttributeMaxDynamicSharedMemorySize,
                         (4 * 128 * LDS + 4 * 128 * LDS) * 2);
    cudaFuncSetAttribute(gemm_mma<64, 8, 1>, cudaFuncAttributeMaxDynamicSharedMemorySize,
                         (4 * 128 * LDS + 4 * 64 * LDS) * 2);

    float* px  = (float*)SYM(g_x);
    float* pq  = (float*)SYM(g_q);
    float* pk  = (float*)SYM(g_k);
    float* pv  = (float*)SYM(g_v);
    float* pS  = (float*)SYM(g_S);
    float* ppp = (float*)SYM(g_pp);
    bf16 *pSh = (bf16*)SYM(g_Sh), *pSl = (bf16*)SYM(g_Sl);
    bf16 *pqh = (bf16*)SYM(g_qh), *pql = (bf16*)SYM(g_ql);
    bf16 *pkh = (bf16*)SYM(g_kh), *pkl = (bf16*)SYM(g_kl);
    bf16 *pvth = (bf16*)SYM(g_vth), *pvtl = (bf16*)SYM(g_vtl);
    bf16 *pah = (bf16*)SYM(g_ah), *pal = (bf16*)SYM(g_al);
    bf16 *pfh = (bf16*)SYM(g_fh), *pfl = (bf16*)SYM(g_fl);
    bf16 *pwqh = (bf16*)SYM(g_wqh), *pwql = (bf16*)SYM(g_wql);
    bf16 *pwkh = (bf16*)SYM(g_wkh), *pwkl = (bf16*)SYM(g_wkl);
    bf16 *pwvh = (bf16*)SYM(g_wvh), *pwvl = (bf16*)SYM(g_wvl);
    bf16 *pwoh = (bf16*)SYM(g_woh), *pwol = (bf16*)SYM(g_wol);
    bf16 *pw1h = (bf16*)SYM(g_w1h), *pw1l = (bf16*)SYM(g_w1l);
    bf16 *pw2h = (bf16*)SYM(g_w2h), *pw2l = (bf16*)SYM(g_w2l);
    bf16 *plmh = (bf16*)SYM(g_lmh), *plml = (bf16*)SYM(g_lml);
    bf16 *ppwh = (bf16*)SYM(g_pwh), *ppwl = (bf16*)SYM(g_pwl);
    bf16 *pimh = (bf16*)SYM(g_imh), *piml = (bf16*)SYM(g_iml);

    // ---- weight prep: transpose + split ----
    dim3 tb(32, 8);
    transpose_split_k<<<dim3(CC/32,  CC/32,  LL), tb>>>(wq, pwqh, pwql, CC, CC);
    transpose_split_k<<<dim3(CC/32,  CC/32,  LL), tb>>>(wk, pwkh, pwkl, CC, CC);
    transpose_split_k<<<dim3(CC/32,  CC/32,  LL), tb>>>(wv, pwvh, pwvl, CC, CC);
    transpose_split_k<<<dim3(CC/32,  CC/32,  LL), tb>>>(wo, pwoh, pwol, CC, CC);
    transpose_split_k<<<dim3(FF_/32, CC/32,  LL), tb>>>(w1, pw1h, pw1l, CC, FF_);
    transpose_split_k<<<dim3(CC/32,  FF_/32, LL), tb>>>(w2, pw2h, pw2l, FF_, CC);
    transpose_split_k<<<dim3(VV/32,  CC/32,  1),  tb>>>(lm_w, plmh, plml, CC, VV);
    split_k<<<(CC*KIM + 255)/256, 256>>>(patch_w, ppwh, ppwl, CC*KIM);

    // ---- patch embedding ----
    im2col_split_k<<<(BB*NPATCH*KIM + 255)/256, 256>>>(images, pimh, piml);
    tc(pimh, piml, ppwh, ppwl, patch_b, nullptr, ppp, nullptr, nullptr,
       BB*NPATCH, CC, KIM, CC, 128);

    // ---- embedding assembly ----
    embed_k<<<BB*TT, 256>>>(text_tokens, tok_emb, txt_pos, img_pos, ppp, px);

    const int M = MTOK;
    for (int l = 0; l < LL; l++) {
        size_t wOff = (size_t)l * CC * CC, w1Off = (size_t)l * CC * FF_;

        layernorm_split_k<<<M, 256>>>(px, ln1_g + l*CC, ln1_b + l*CC, pah, pal);

        tc(pah, pal, pwqh + wOff, pwql + wOff, nullptr, nullptr, pq, nullptr, nullptr,
           M, CC, CC, CC, 128);
        tc(pah, pal, pwkh + wOff, pwkl + wOff, nullptr, nullptr, pk, nullptr, nullptr,
           M, CC, CC, CC, 128);
        tc(pah, pal, pwvh + wOff, pwvl + wOff, nullptr, nullptr, pv, nullptr, nullptr,
           M, CC, CC, CC, 128);

        repack_qkv_k<<<M*CC/256, 256>>>(pq, pk, pv, pqh, pql, pkh, pkl, pvth, pvtl);

        // scores: per (b,h)  S = 0.125 * Q @ K^T   [T,T], tri-skip
        tc(pqh, pql, pkh, pkl, nullptr, nullptr, pS, nullptr, nullptr,
           TT, TT, HD, TT, 128, 0.125f, 0, 0, /*tri*/1,
           BB*HH, 1,
           (long long)TT*HD, 0, (long long)TT*HD, 0, (long long)TT*TT, 0);

        softmax_split_k<<<BB*HH*TT, 256>>>(pS, pSh, pSl);

        // A@V: per (b,h)  O = P @ V^T(v stored [hd,t]) -> split bf16 at [b,t,h,d]
        tc(pSh, pSl, pvth, pvtl, nullptr, nullptr, nullptr, pah, pal,
           TT, HD, TT, CC, 64, 1.f, 0, /*kLimit*/1, 0,
           BB*HH, HH,
           (long long)HH*TT*TT, (long long)TT*TT,
           (long long)HH*HD*TT, (long long)HD*TT,
           (long long)TT*CC, HD);

        // out proj + bias + residual -> x
        tc(pah, pal, pwoh + wOff, pwol + wOff, bo + l*CC, px, px, nullptr, nullptr,
           M, CC, CC, CC, 128);

        layernorm_split_k<<<M, 256>>>(px, ln2_g + l*CC, ln2_b + l*CC, pah, pal);

        // ffn
        tc(pah, pal, pw1h + w1Off, pw1l + w1Off, b1 + l*FF_, nullptr,
           nullptr, pfh, pfl, M, FF_, CC, FF_, 128, 1.f, /*relu*/1);
        tc(pfh, pfl, pw2h + w1Off, pw2l + w1Off, b2 + l*CC, px, px, nullptr, nullptr,
           M, CC, FF_, CC, 128);
    }

    // ---- final LN + LM head ----
    layernorm_split_k<<<M, 256>>>(px, lnf_g, lnf_b, pah, pal);
    tc(pah, pal, plmh, plml, lm_b, nullptr, out, nullptr, nullptr,
       M, VV, CC, VV, 128);
}

// round 4
// speedup vs baseline: 2.9385x; 1.0958x over previous
#include <cuda_runtime.h>
#include <cuda_bf16.h>
#include <cstdint>

typedef __nv_bfloat16 bf16;

// ---------------- problem constants ----------------
#define BB    4
#define TT    1024
#define CC    1024
#define HH    16
#define HD    64
#define LL    6
#define VV    16000
#define FF_   4096
#define TTXT  580
#define NPATCH 441
#define KIM   768
#define IMG   336
#define PATCH 16
#define MTOK  (BB*TT)          // 4096

// ---------------- scratch (device globals; no allocation) ----------------
__device__ float g_x  [(size_t)MTOK*CC];
__device__ float g_qkv[(size_t)MTOK*3*CC];
__device__ float g_S  [(size_t)BB*HH*TT*TT];
__device__ float g_pp [(size_t)BB*NPATCH*CC];

__device__ bf16 g_Sh[(size_t)BB*HH*TT*TT];
__device__ bf16 g_Sl[(size_t)BB*HH*TT*TT];
__device__ bf16 g_qh[(size_t)MTOK*CC], g_ql[(size_t)MTOK*CC];
__device__ bf16 g_kh[(size_t)MTOK*CC], g_kl[(size_t)MTOK*CC];
__device__ bf16 g_vth[(size_t)MTOK*CC], g_vtl[(size_t)MTOK*CC];
__device__ bf16 g_ah[(size_t)MTOK*CC], g_al[(size_t)MTOK*CC];
__device__ bf16 g_fh[(size_t)MTOK*FF_], g_fl[(size_t)MTOK*FF_];

__device__ bf16 g_wqkvh[(size_t)LL*3*CC*CC], g_wqkvl[(size_t)LL*3*CC*CC];
__device__ bf16 g_woh[(size_t)LL*CC*CC], g_wol[(size_t)LL*CC*CC];
__device__ bf16 g_w1h[(size_t)LL*CC*FF_], g_w1l[(size_t)LL*CC*FF_];
__device__ bf16 g_w2h[(size_t)LL*CC*FF_], g_w2l[(size_t)LL*CC*FF_];
__device__ bf16 g_lmh[(size_t)CC*VV],    g_lml[(size_t)CC*VV];
__device__ bf16 g_pwh[(size_t)CC*KIM],   g_pwl[(size_t)CC*KIM];
__device__ bf16 g_imh[(size_t)BB*NPATCH*KIM], g_iml[(size_t)BB*NPATCH*KIM];

// ---------------- low-level helpers ----------------
__device__ __forceinline__ uint32_t smem_u32(const void* p) {
    uint32_t a;
    asm("{ .reg .u64 t; cvta.to.shared.u64 t, %1; cvt.u32.u64 %0, t; }" : "=r"(a) : "l"(p));
    return a;
}
__device__ __forceinline__ void cpa16(uint32_t dst, const void* src, int szbytes) {
    asm volatile("cp.async.cg.shared.global [%0], [%1], 16, %2;"
                 :: "r"(dst), "l"(src), "r"(szbytes) : "memory");
}
__device__ __forceinline__ void ldsm4(uint32_t (&r)[4], uint32_t addr) {
    asm volatile("ldmatrix.sync.aligned.m8n8.x4.shared.b16 {%0,%1,%2,%3}, [%4];"
                 : "=r"(r[0]), "=r"(r[1]), "=r"(r[2]), "=r"(r[3]) : "r"(addr));
}
__device__ __forceinline__ void mma_bf16(float (&d)[4], const uint32_t (&a)[4],
                                         uint32_t b0, uint32_t b1) {
    asm volatile("mma.sync.aligned.m16n8k16.row.col.f32.bf16.bf16.f32 "
                 "{%0,%1,%2,%3}, {%4,%5,%6,%7}, {%8,%9}, {%0,%1,%2,%3};"
                 : "+f"(d[0]), "+f"(d[1]), "+f"(d[2]), "+f"(d[3])
                 : "r"(a[0]), "r"(a[1]), "r"(a[2]), "r"(a[3]), "r"(b0), "r"(b1));
}

// ---------------- split-bf16 tensor-core GEMM (mma.sync) ----------------
// C = alpha * (Ah+Al)[M,K] @ (Bh+Bl)[N,K]^T  (+bias/res/relu); A,B row-major [*,K]
#define LDS 40
#define BM  128

template<int BN, int WROWS, int WCOLS>
__global__ __launch_bounds__(256, 2)
void gemm_mma(const bf16* __restrict__ Ah, const bf16* __restrict__ Al,
              const bf16* __restrict__ Bh, const bf16* __restrict__ Bl,
              const float* __restrict__ bias, const float* __restrict__ res,
              float* __restrict__ outF, bf16* __restrict__ outH, bf16* __restrict__ outL,
              int M, int Nfull, int K, int ldc,
              long long ab1, long long ab2, long long bb1, long long bb2,
              long long cb1, long long cb2, int Hdiv,
              float alpha, int relu, int kLimit, int tri)
{
    constexpr int WM = BM / WROWS;
    constexpr int WN = BN / WCOLS;
    constexpr int MI = WM / 16;
    constexpr int NI = WN / 8;
    constexpr int ASZ = BM * LDS;
    constexpr int BSZ = BN * LDS;

    const int m0 = blockIdx.y * BM;
    const int n0 = blockIdx.x * BN;
    if (tri && n0 > m0 + (BM - 1)) return;

    const int z = blockIdx.z, zb = z / Hdiv, zh = z % Hdiv;
    Ah += (long long)zb*ab1 + (long long)zh*ab2;
    Al += (long long)zb*ab1 + (long long)zh*ab2;
    Bh += (long long)zb*bb1 + (long long)zh*bb2;
    Bl += (long long)zb*bb1 + (long long)zh*bb2;
    const long long coff = (long long)zb*cb1 + (long long)zh*cb2;

    extern __shared__ bf16 sm[];
    const uint32_t sbase = smem_u32(sm);

    const int tid = threadIdx.x;
    int Keff = K;
    if (kLimit) { int kl = m0 + BM; if (kl < Keff) Keff = kl; }
    const int nch = Keff >> 5;

    auto load_stage = [&](int st, int k0) {
        #pragma unroll
        for (int i = tid; i < BM * 4; i += 256) {
            int r = i >> 2, c8 = (i & 3) << 3;
            int gr = m0 + r;
            int ok = (gr < M) ? 16 : 0;
            if (gr >= M) gr = m0;
            size_t go = (size_t)gr * K + k0 + c8;
            uint32_t so = (uint32_t)((st * ASZ + r * LDS + c8) * 2);
            cpa16(sbase + so, Ah + go, ok);
            cpa16(sbase + so + 2 * ASZ * 2, Al + go, ok);
        }
        #pragma unroll
        for (int i = tid; i < BN * 4; i += 256) {
            int r = i >> 2, c8 = (i & 3) << 3;
            int gn = n0 + r;
            int ok = (gn < Nfull) ? 16 : 0;
            if (gn >= Nfull) gn = n0;
            size_t go = (size_t)gn * K + k0 + c8;
            uint32_t so = (uint32_t)((4 * ASZ + st * BSZ + r * LDS + c8) * 2);
            cpa16(sbase + so, Bh + go, ok);
            cpa16(sbase + so + 2 * BSZ * 2, Bl + go, ok);
        }
        asm volatile("cp.async.commit_group;" ::: "memory");
    };

    const int wid = tid >> 5, lane = tid & 31;
    const int wr = wid % WROWS, wc = wid / WROWS;
    const int wmBase = wr * WM, wnBase = wc * WN;

    float acc[MI][NI][4];
    #pragma unroll
    for (int mi = 0; mi < MI; mi++)
        #pragma unroll
        for (int ni = 0; ni < NI; ni++)
            #pragma unroll
            for (int j = 0; j < 4; j++) acc[mi][ni][j] = 0.f;

    load_stage(0, 0);

    for (int ch = 0; ch < nch; ch++) {
        if (ch + 1 < nch) {
            load_stage((ch + 1) & 1, (ch + 1) << 5);
            asm volatile("cp.async.wait_group 1;" ::: "memory");
        } else {
            asm volatile("cp.async.wait_group 0;" ::: "memory");
        }
        __syncthreads();

        const int st = ch & 1;
        const uint32_t aHb = sbase + (uint32_t)(st * ASZ * 2);
        const uint32_t aLb = aHb + (uint32_t)(2 * ASZ * 2);
        const uint32_t bHb = sbase + (uint32_t)((4 * ASZ + st * BSZ) * 2);
        const uint32_t bLb = bHb + (uint32_t)(2 * BSZ * 2);

        #pragma unroll
        for (int kk = 0; kk < 2; kk++) {
            const int colOff = kk * 16 + ((lane >> 4) << 3);
            uint32_t afH[MI][4], afL[MI][4];
            #pragma unroll
            for (int mi = 0; mi < MI; mi++) {
                uint32_t off = (uint32_t)(((wmBase + mi * 16 + (lane & 15)) * LDS + colOff) * 2);
                ldsm4(afH[mi], aHb + off);
                ldsm4(afL[mi], aLb + off);
            }
            #pragma unroll
            for (int nj = 0; nj < NI / 2; nj++) {
                uint32_t off = (uint32_t)(((wnBase + nj * 16 + (lane & 15)) * LDS + colOff) * 2);
                uint32_t bfH[4], bfL[4];
                ldsm4(bfH, bHb + off);
                ldsm4(bfL, bLb + off);
                #pragma unroll
                for (int mi = 0; mi < MI; mi++) {
                    mma_bf16(acc[mi][2*nj],   afH[mi], bfH[0], bfH[2]);
                    mma_bf16(acc[mi][2*nj],   afH[mi], bfL[0], bfL[2]);
                    mma_bf16(acc[mi][2*nj],   afL[mi], bfH[0], bfH[2]);
                    mma_bf16(acc[mi][2*nj+1], afH[mi], bfH[1], bfH[3]);
                    mma_bf16(acc[mi][2*nj+1], afH[mi], bfL[1], bfL[3]);
                    mma_bf16(acc[mi][2*nj+1], afL[mi], bfH[1], bfH[3]);
                }
            }
        }
        __syncthreads();
    }

    // epilogue
    const int g = lane >> 2, t4 = lane & 3;
    #pragma unroll
    for (int mi = 0; mi < MI; mi++) {
        #pragma unroll
        for (int ni = 0; ni < NI; ni++) {
            int col = n0 + wnBase + ni * 8 + t4 * 2;
            if (col >= Nfull) continue;
            #pragma unroll
            for (int half = 0; half < 2; half++) {
                int row = m0 + wmBase + mi * 16 + g + half * 8;
                if (row >= M) continue;
                float v0 = acc[mi][ni][half * 2 + 0] * alpha;
                float v1 = acc[mi][ni][half * 2 + 1] * alpha;
                long long base = coff + (long long)row * ldc + col;
                if (bias) { v0 += bias[col]; v1 += bias[col + 1]; }
                if (res)  { v0 += res[base]; v1 += res[base + 1]; }
                if (relu) { v0 = fmaxf(v0, 0.f); v1 = fmaxf(v1, 0.f); }
                if (outF) *(float2*)(outF + base) = make_float2(v0, v1);
                if (outH) {
                    bf16 h0 = __float2bfloat16(v0), h1 = __float2bfloat16(v1);
                    float r0 = v0 - __bfloat162float(h0), r1 = v1 - __bfloat162float(h1);
                    bf16 l0 = __float2bfloat16(r0), l1 = __float2bfloat16(r1);
                    uint32_t hw = (uint32_t)__bfloat16_as_ushort(h0) |
                                  ((uint32_t)__bfloat16_as_ushort(h1) << 16);
                    uint32_t lw = (uint32_t)__bfloat16_as_ushort(l0) |
                                  ((uint32_t)__bfloat16_as_ushort(l1) << 16);
                    *(uint32_t*)(outH + base) = hw;
                    *(uint32_t*)(outL + base) = lw;
                }
            }
        }
    }
}

// ---------------- block reductions ----------------
__device__ __forceinline__ float blockReduceSum256(float v, float* sh) {
    #pragma unroll
    for (int o = 16; o > 0; o >>= 1) v += __shfl_xor_sync(0xffffffffu, v, o);
    int w = threadIdx.x >> 5;
    if ((threadIdx.x & 31) == 0) sh[w] = v;
    __syncthreads();
    if (threadIdx.x < 8) {
        v = sh[threadIdx.x];
        #pragma unroll
        for (int o = 4; o > 0; o >>= 1) v += __shfl_xor_sync(0xffu, v, o);
        if (threadIdx.x == 0) sh[0] = v;
    }
    __syncthreads();
    float r = sh[0]; __syncthreads(); return r;
}
__device__ __forceinline__ float blockReduceMax256(float v, float* sh) {
    #pragma unroll
    for (int o = 16; o > 0; o >>= 1) v = fmaxf(v, __shfl_xor_sync(0xffffffffu, v, o));
    int w = threadIdx.x >> 5;
    if ((threadIdx.x & 31) == 0) sh[w] = v;
    __syncthreads();
    if (threadIdx.x < 8) {
        v = sh[threadIdx.x];
        #pragma unroll
        for (int o = 4; o > 0; o >>= 1) v = fmaxf(v, __shfl_xor_sync(0xffu, v, o));
        if (threadIdx.x == 0) sh[0] = v;
    }
    __syncthreads();
    float r = sh[0]; __syncthreads(); return r;
}

__device__ __forceinline__ void split_store(bf16* H, bf16* L, size_t i, float v) {
    bf16 h = __float2bfloat16(v);
    H[i] = h;
    L[i] = __float2bfloat16(v - __bfloat162float(h));
}

// ---------------- layernorm -> split bf16 ----------------
__global__ __launch_bounds__(256)
void layernorm_split_k(const float* __restrict__ x, const float* __restrict__ g,
                       const float* __restrict__ b, bf16* __restrict__ oh, bf16* __restrict__ ol)
{
    __shared__ float sh[8];
    const size_t row = blockIdx.x;
    const float* xr = x + row * CC;
    const int c = threadIdx.x * 4;
    float4 xv = *(const float4*)(xr + c);
    float s  = xv.x + xv.y + xv.z + xv.w;
    float ss = xv.x*xv.x + xv.y*xv.y + xv.z*xv.z + xv.w*xv.w;
    s = blockReduceSum256(s, sh);
    ss = blockReduceSum256(ss, sh);
    float mean = s * (1.f / CC);
    float var = ss * (1.f / CC) - mean * mean;
    float inv = rsqrtf(var + 1e-5f);
    float4 gv = *(const float4*)(g + c);
    float4 bv = *(const float4*)(b + c);
    size_t base = row * CC + c;
    split_store(oh, ol, base + 0, (xv.x - mean) * inv * gv.x + bv.x);
    split_store(oh, ol, base + 1, (xv.y - mean) * inv * gv.y + bv.y);
    split_store(oh, ol, base + 2, (xv.z - mean) * inv * gv.z + bv.z);
    split_store(oh, ol, base + 3, (xv.w - mean) * inv * gv.w + bv.w);
}

// ---------------- causal softmax -> split bf16 ----------------
__global__ __launch_bounds__(256)
void softmax_split_k(const float* __restrict__ S, bf16* __restrict__ Ph, bf16* __restrict__ Pl)
{
    __shared__ float sh[8];
    const int r = blockIdx.x;
    const int i = r & (TT - 1);
    const float* row = S + (size_t)r * TT;
    const int tid = threadIdx.x;
    float vals[4];
    float mx = -1e30f;
    #pragma unroll
    for (int u = 0; u < 4; u++) {
        int j = tid + (u << 8);
        vals[u] = (j <= i) ? row[j] : -1e30f;
        mx = fmaxf(mx, vals[u]);
    }
    mx = blockReduceMax256(mx, sh);
    float sum = 0.f;
    #pragma unroll
    for (int u = 0; u < 4; u++) {
        int j = tid + (u << 8);
        float e = (j <= i) ? __expf(vals[u] - mx) : 0.f;
        vals[u] = e; sum += e;
    }
    sum = blockReduceSum256(sum, sh);
    float invs = 1.f / sum;
    #pragma unroll
    for (int u = 0; u < 4; u++) {
        int j = tid + (u << 8);
        split_store(Ph, Pl, (size_t)r * TT + j, vals[u] * invs);
    }
}

// ---------------- repack fused qkv -> q,k [B,H,T,HD] split; v -> [B,H,HD,T] split ----------------
__global__ __launch_bounds__(256)
void repack_qkv_k(const float* __restrict__ qkv,
                  bf16* qh, bf16* ql, bf16* kh, bf16* kl, bf16* vth, bf16* vtl)
{
    size_t idx = (size_t)blockIdx.x * 256 + threadIdx.x;   // over M * 3C
    int c3 = idx % (3 * CC);
    size_t bt = idx / (3 * CC);
    int t = bt & 1023;
    int b = bt >> 10;
    int which = c3 >> 10;
    int c = c3 & 1023;
    int h = c >> 6, d = c & 63;
    float v = qkv[idx];
    if (which == 0) {
        size_t o1 = (((size_t)(b * HH + h)) * TT + t) * HD + d;
        split_store(qh, ql, o1, v);
    } else if (which == 1) {
        size_t o1 = (((size_t)(b * HH + h)) * TT + t) * HD + d;
        split_store(kh, kl, o1, v);
    } else {
        size_t o2 = (((size_t)(b * HH + h)) * HD + d) * TT + t;
        split_store(vth, vtl, o2, v);
    }
}

// ---------------- weight transpose + split: W[K,N] -> Wt[N,K] hi/lo ----------------
// in z-offset: z*K*N ; out z-offset: z*zOutStride (element units)
__global__ void transpose_split_k(const float* __restrict__ W, bf16* __restrict__ hi,
                                  bf16* __restrict__ lo, int K, int N, long long zOutStride)
{
    __shared__ float t[32][33];
    W  += (size_t)blockIdx.z * K * N;
    hi += (size_t)blockIdx.z * zOutStride;
    lo += (size_t)blockIdx.z * zOutStride;
    int k0 = blockIdx.y * 32, n0 = blockIdx.x * 32;
    int tx = threadIdx.x, ty = threadIdx.y;
    #pragma unroll
    for (int i = 0; i < 32; i += 8)
        t[ty + i][tx] = W[(size_t)(k0 + ty + i) * N + n0 + tx];
    __syncthreads();
    #pragma unroll
    for (int i = 0; i < 32; i += 8)
        split_store(hi, lo, (size_t)(n0 + ty + i) * K + k0 + tx, t[tx][ty + i]);
}

// ---------------- elementwise split ----------------
__global__ void split_k(const float* __restrict__ W, bf16* hi, bf16* lo, int n)
{
    int idx = blockIdx.x * 256 + threadIdx.x;
    if (idx < n) split_store(hi, lo, idx, W[idx]);
}

// ---------------- im2col + split ----------------
__global__ void im2col_split_k(const float* __restrict__ img, bf16* hi, bf16* lo)
{
    int idx = blockIdx.x * 256 + threadIdx.x;
    if (idx >= BB * NPATCH * KIM) return;
    int k = idx % KIM;
    int bn = idx / KIM;
    int n = bn % NPATCH;
    int b = bn / NPATCH;
    int ci = k >> 8;
    int rr = k & 255;
    int kh = rr >> 4;
    int kw = rr & 15;
    int ph = n / 21, pw = n % 21;
    float v = img[(((size_t)b * 3 + ci) * IMG + ph * PATCH + kh) * IMG + pw * PATCH + kw];
    split_store(hi, lo, idx, v);
}

// ---------------- embedding assembly ----------------
__global__ __launch_bounds__(256)
void embed_k(const int* __restrict__ toks, const float* __restrict__ tok_emb,
             const float* __restrict__ txt_pos, const float* __restrict__ img_pos,
             const float* __restrict__ p, float* __restrict__ x)
{
    const int bt = blockIdx.x;
    const int b = bt >> 10;
    const int t = bt & 1023;
    const int c = threadIdx.x * 4;
    const float* src;
    const float* extra = nullptr;
    if (t == 0)      src = tok_emb + 1 * CC;
    else if (t == 1) src = tok_emb + 8 * CC;
    else if (t < 443) {
        int n = t - 2;
        src = p + ((size_t)(b * NPATCH + n)) * CC;
        extra = img_pos + (size_t)n * CC;
    }
    else if (t == 443) src = tok_emb + 9 * CC;
    else {
        int tok = toks[b * TTXT + (t - 444)];
        src = tok_emb + (size_t)tok * CC;
    }
    float4 v = *(const float4*)(src + c);
    float4 tp = *(const float4*)(txt_pos + (size_t)t * CC + c);
    v.x += tp.x; v.y += tp.y; v.z += tp.z; v.w += tp.w;
    if (extra) {
        float4 e = *(const float4*)(extra + c);
        v.x += e.x; v.y += e.y; v.z += e.z; v.w += e.w;
    }
    *(float4*)(x + (size_t)bt * CC + c) = v;
}

// ---------------- host-side GEMM launcher ----------------
static inline void tc(const bf16* Ah, const bf16* Al, const bf16* Bh, const bf16* Bl,
                      const float* bias, const float* res,
                      float* outF, bf16* outH, bf16* outL,
                      int M, int N, int K, int ldc, int Ntile,
                      float alpha = 1.f, int relu = 0, int kLimit = 0, int tri = 0,
                      int nz = 1, int Hdiv = 1,
                      long long ab1 = 0, long long ab2 = 0,
                      long long bb1 = 0, long long bb2 = 0,
                      long long cb1 = 0, long long cb2 = 0)
{
    dim3 grid((N + Ntile - 1) / Ntile, (M + 127) / 128, nz);
    if (Ntile == 64) {
        size_t sh = (size_t)(4 * 128 * LDS + 4 * 64 * LDS) * 2;
        gemm_mma<64, 8, 1><<<grid, 256, sh>>>(Ah, Al, Bh, Bl, bias, res, outF, outH, outL,
            M, N, K, ldc, ab1, ab2, bb1, bb2, cb1, cb2, Hdiv, alpha, relu, kLimit, tri);
    } else {
        size_t sh = (size_t)(4 * 128 * LDS + 4 * 128 * LDS) * 2;
        gemm_mma<128, 4, 2><<<grid, 256, sh>>>(Ah, Al, Bh, Bl, bias, res, outF, outH, outL,
            M, N, K, ldc, ab1, ab2, bb1, bb2, cb1, cb2, Hdiv, alpha, relu, kLimit, tri);
    }
}

#define SYM(name) ({ void* _p; cudaGetSymbolAddress(&_p, name); _p; })

extern "C" void kernel_launch(void* const* d_in, const int* in_sizes, int n_in,
                              void* d_out, int out_size)
{
    const int*   text_tokens = (const int*)  d_in[0];
    const float* images      = (const float*)d_in[1];
    const float* tok_emb     = (const float*)d_in[2];
    const float* txt_pos     = (const float*)d_in[3];
    const float* img_pos     = (const float*)d_in[4];
    const float* patch_w     = (const float*)d_in[5];
    const float* patch_b     = (const float*)d_in[6];
    const float* ln1_g       = (const float*)d_in[7];
    const float* ln1_b       = (const float*)d_in[8];
    const float* wq          = (const float*)d_in[9];
    const float* wk          = (const float*)d_in[10];
    const float* wv          = (const float*)d_in[11];
    const float* wo          = (const float*)d_in[12];
    const float* bo          = (const float*)d_in[13];
    const float* ln2_g       = (const float*)d_in[14];
    const float* ln2_b       = (const float*)d_in[15];
    const float* w1          = (const float*)d_in[16];
    const float* b1          = (const float*)d_in[17];
    const float* w2          = (const float*)d_in[18];
    const float* b2          = (const float*)d_in[19];
    const float* lnf_g       = (const float*)d_in[20];
    const float* lnf_b       = (const float*)d_in[21];
    const float* lm_w        = (const float*)d_in[22];
    const float* lm_b        = (const float*)d_in[23];
    float* out = (float*)d_out;

    cudaFuncSetAttribute(gemm_mma<128, 4, 2>, cudaFuncAttributeMaxDynamicSharedMemorySize,
                         (4 * 128 * LDS + 4 * 128 * LDS) * 2);
    cudaFuncSetAttribute(gemm_mma<64, 8, 1>, cudaFuncAttributeMaxDynamicSharedMemorySize,
                         (4 * 128 * LDS + 4 * 64 * LDS) * 2);

    float* px   = (float*)SYM(g_x);
    float* pqkv = (float*)SYM(g_qkv);
    float* pS   = (float*)SYM(g_S);
    float* ppp  = (float*)SYM(g_pp);
    bf16 *pSh = (bf16*)SYM(g_Sh), *pSl = (bf16*)SYM(g_Sl);
    bf16 *pqh = (bf16*)SYM(g_qh), *pql = (bf16*)SYM(g_ql);
    bf16 *pkh = (bf16*)SYM(g_kh), *pkl = (bf16*)SYM(g_kl);
    bf16 *pvth = (bf16*)SYM(g_vth), *pvtl = (bf16*)SYM(g_vtl);
    bf16 *pah = (bf16*)SYM(g_ah), *pal = (bf16*)SYM(g_al);
    bf16 *pfh = (bf16*)SYM(g_fh), *pfl = (bf16*)SYM(g_fl);
    bf16 *pwqkvh = (bf16*)SYM(g_wqkvh), *pwqkvl = (bf16*)SYM(g_wqkvl);
    bf16 *pwoh = (bf16*)SYM(g_woh), *pwol = (bf16*)SYM(g_wol);
    bf16 *pw1h = (bf16*)SYM(g_w1h), *pw1l = (bf16*)SYM(g_w1l);
    bf16 *pw2h = (bf16*)SYM(g_w2h), *pw2l = (bf16*)SYM(g_w2l);
    bf16 *plmh = (bf16*)SYM(g_lmh), *plml = (bf16*)SYM(g_lml);
    bf16 *ppwh = (bf16*)SYM(g_pwh), *ppwl = (bf16*)SYM(g_pwl);
    bf16 *pimh = (bf16*)SYM(g_imh), *piml = (bf16*)SYM(g_iml);

    // ---- weight prep: transpose + split (q,k,v fused into [3C, C] per layer) ----
    dim3 tb(32, 8);
    const long long QKV_Z = (long long)3 * CC * CC;
    transpose_split_k<<<dim3(CC/32,  CC/32,  LL), tb>>>(wq, pwqkvh,            pwqkvl,            CC, CC, QKV_Z);
    transpose_split_k<<<dim3(CC/32,  CC/32,  LL), tb>>>(wk, pwqkvh + CC*CC,    pwqkvl + CC*CC,    CC, CC, QKV_Z);
    transpose_split_k<<<dim3(CC/32,  CC/32,  LL), tb>>>(wv, pwqkvh + 2*CC*CC,  pwqkvl + 2*CC*CC,  CC, CC, QKV_Z);
    transpose_split_k<<<dim3(CC/32,  CC/32,  LL), tb>>>(wo, pwoh, pwol, CC, CC, (long long)CC*CC);
    transpose_split_k<<<dim3(FF_/32, CC/32,  LL), tb>>>(w1, pw1h, pw1l, CC, FF_, (long long)CC*FF_);
    transpose_split_k<<<dim3(CC/32,  FF_/32, LL), tb>>>(w2, pw2h, pw2l, FF_, CC, (long long)CC*FF_);
    transpose_split_k<<<dim3(VV/32,  CC/32,  1),  tb>>>(lm_w, plmh, plml, CC, VV, 0);
    split_k<<<(CC*KIM + 255)/256, 256>>>(patch_w, ppwh, ppwl, CC*KIM);

    // ---- patch embedding ----
    im2col_split_k<<<(BB*NPATCH*KIM + 255)/256, 256>>>(images, pimh, piml);
    tc(pimh, piml, ppwh, ppwl, patch_b, nullptr, ppp, nullptr, nullptr,
       BB*NPATCH, CC, KIM, CC, 128);

    // ---- embedding assembly ----
    embed_k<<<BB*TT, 256>>>(text_tokens, tok_emb, txt_pos, img_pos, ppp, px);

    const int M = MTOK;
    for (int l = 0; l < LL; l++) {
        size_t wOff = (size_t)l * CC * CC, w1Off = (size_t)l * CC * FF_;
        size_t qkvOff = (size_t)l * 3 * CC * CC;

        layernorm_split_k<<<M, 256>>>(px, ln1_g + l*CC, ln1_b + l*CC, pah, pal);

        // fused q|k|v projection: [M, 3C]
        tc(pah, pal, pwqkvh + qkvOff, pwqkvl + qkvOff, nullptr, nullptr,
           pqkv, nullptr, nullptr, M, 3*CC, CC, 3*CC, 128);

        repack_qkv_k<<<M*3*CC/256, 256>>>(pqkv, pqh, pql, pkh, pkl, pvth, pvtl);

        // scores: per (b,h)  S = 0.125 * Q @ K^T   [T,T], tri-skip
        tc(pqh, pql, pkh, pkl, nullptr, nullptr, pS, nullptr, nullptr,
           TT, TT, HD, TT, 128, 0.125f, 0, 0, /*tri*/1,
           BB*HH, 1,
           (long long)TT*HD, 0, (long long)TT*HD, 0, (long long)TT*TT, 0);

        softmax_split_k<<<BB*HH*TT, 256>>>(pS, pSh, pSl);

        // A@V: per (b,h)  O = P @ V^T(v stored [hd,t]) -> split bf16 at [b,t,h,d]
        tc(pSh, pSl, pvth, pvtl, nullptr, nullptr, nullptr, pah, pal,
           TT, HD, TT, CC, 64, 1.f, 0, /*kLimit*/1, 0,
           BB*HH, HH,
           (long long)HH*TT*TT, (long long)TT*TT,
           (long long)HH*HD*TT, (long long)HD*TT,
           (long long)TT*CC, HD);

        // out proj + bias + residual -> x
        tc(pah, pal, pwoh + wOff, pwol + wOff, bo + l*CC, px, px, nullptr, nullptr,
           M, CC, CC, CC, 128);

        layernorm_split_k<<<M, 256>>>(px, ln2_g + l*CC, ln2_b + l*CC, pah, pal);

        // ffn
        tc(pah, pal, pw1h + w1Off, pw1l + w1Off, b1 + l*FF_, nullptr,
           nullptr, pfh, pfl, M, FF_, CC, FF_, 128, 1.f, /*relu*/1);
        tc(pfh, pfl, pw2h + w1Off, pw2l + w1Off, b2 + l*CC, px, px, nullptr, nullptr,
           M, CC, FF_, CC, 128);
    }

    // ---- final LN + LM head ----
    layernorm_split_k<<<M, 256>>>(px, lnf_g, lnf_b, pah, pal);
    tc(pah, pal, plmh, plml, lm_b, nullptr, out, nullptr, nullptr,
       M, VV, CC, VV, 128);
}

// round 5
// speedup vs baseline: 3.1554x; 1.0738x over previous
#include <cuda_runtime.h>
#include <cuda_bf16.h>
#include <cstdint>

typedef __nv_bfloat16 bf16;

// ---------------- problem constants ----------------
#define BB    4
#define TT    1024
#define CC    1024
#define HH    16
#define HD    64
#define LL    6
#define VV    16000
#define FF_   4096
#define TTXT  580
#define NPATCH 441
#define KIM   768
#define IMG   336
#define PATCH 16
#define MTOK  (BB*TT)          // 4096

// ---------------- scratch (device globals; no allocation) ----------------
__device__ float g_x  [(size_t)MTOK*CC];
__device__ float g_qkv[(size_t)MTOK*3*CC];
__device__ float g_pp [(size_t)BB*NPATCH*CC];

__device__ bf16 g_qh[(size_t)MTOK*CC], g_ql[(size_t)MTOK*CC];
__device__ bf16 g_kh[(size_t)MTOK*CC], g_kl[(size_t)MTOK*CC];
__device__ bf16 g_vth[(size_t)MTOK*CC], g_vtl[(size_t)MTOK*CC];
__device__ bf16 g_ah[(size_t)MTOK*CC], g_al[(size_t)MTOK*CC];
__device__ bf16 g_fh[(size_t)MTOK*FF_], g_fl[(size_t)MTOK*FF_];

__device__ bf16 g_wqkvh[(size_t)LL*3*CC*CC], g_wqkvl[(size_t)LL*3*CC*CC];
__device__ bf16 g_woh[(size_t)LL*CC*CC], g_wol[(size_t)LL*CC*CC];
__device__ bf16 g_w1h[(size_t)LL*CC*FF_], g_w1l[(size_t)LL*CC*FF_];
__device__ bf16 g_w2h[(size_t)LL*CC*FF_], g_w2l[(size_t)LL*CC*FF_];
__device__ bf16 g_lmh[(size_t)CC*VV],    g_lml[(size_t)CC*VV];
__device__ bf16 g_pwh[(size_t)CC*KIM],   g_pwl[(size_t)CC*KIM];
__device__ bf16 g_imh[(size_t)BB*NPATCH*KIM], g_iml[(size_t)BB*NPATCH*KIM];

// ---------------- low-level helpers ----------------
__device__ __forceinline__ uint32_t smem_u32(const void* p) {
    uint32_t a;
    asm("{ .reg .u64 t; cvta.to.shared.u64 t, %1; cvt.u32.u64 %0, t; }" : "=r"(a) : "l"(p));
    return a;
}
__device__ __forceinline__ void cpa16(uint32_t dst, const void* src, int szbytes) {
    asm volatile("cp.async.cg.shared.global [%0], [%1], 16, %2;"
                 :: "r"(dst), "l"(src), "r"(szbytes) : "memory");
}
__device__ __forceinline__ void ldsm4(uint32_t (&r)[4], uint32_t addr) {
    asm volatile("ldmatrix.sync.aligned.m8n8.x4.shared.b16 {%0,%1,%2,%3}, [%4];"
                 : "=r"(r[0]), "=r"(r[1]), "=r"(r[2]), "=r"(r[3]) : "r"(addr));
}
__device__ __forceinline__ void mma_bf16(float (&d)[4], const uint32_t (&a)[4],
                                         uint32_t b0, uint32_t b1) {
    asm volatile("mma.sync.aligned.m16n8k16.row.col.f32.bf16.bf16.f32 "
                 "{%0,%1,%2,%3}, {%4,%5,%6,%7}, {%8,%9}, {%0,%1,%2,%3};"
                 : "+f"(d[0]), "+f"(d[1]), "+f"(d[2]), "+f"(d[3])
                 : "r"(a[0]), "r"(a[1]), "r"(a[2]), "r"(a[3]), "r"(b0), "r"(b1));
}
__device__ __forceinline__ uint32_t pack_split(float v0, float v1, uint32_t& lw) {
    bf16 h0 = __float2bfloat16(v0), h1 = __float2bfloat16(v1);
    float r0 = v0 - __bfloat162float(h0), r1 = v1 - __bfloat162float(h1);
    bf16 l0 = __float2bfloat16(r0), l1 = __float2bfloat16(r1);
    lw = (uint32_t)__bfloat16_as_ushort(l0) | ((uint32_t)__bfloat16_as_ushort(l1) << 16);
    return (uint32_t)__bfloat16_as_ushort(h0) | ((uint32_t)__bfloat16_as_ushort(h1) << 16);
}

// ---------------- split-bf16 tensor-core GEMM (mma.sync) ----------------
#define LDS 40
#define BM  128

template<int BN, int WROWS, int WCOLS>
__global__ __launch_bounds__(256, 2)
void gemm_mma(const bf16* __restrict__ Ah, const bf16* __restrict__ Al,
              const bf16* __restrict__ Bh, const bf16* __restrict__ Bl,
              const float* __restrict__ bias, const float* __restrict__ res,
              float* __restrict__ outF, bf16* __restrict__ outH, bf16* __restrict__ outL,
              int M, int Nfull, int K, int ldc,
              long long ab1, long long ab2, long long bb1, long long bb2,
              long long cb1, long long cb2, int Hdiv,
              float alpha, int relu, int kLimit, int tri)
{
    constexpr int WM = BM / WROWS;
    constexpr int WN = BN / WCOLS;
    constexpr int MI = WM / 16;
    constexpr int NI = WN / 8;
    constexpr int ASZ = BM * LDS;
    constexpr int BSZ = BN * LDS;

    const int m0 = blockIdx.y * BM;
    const int n0 = blockIdx.x * BN;
    if (tri && n0 > m0 + (BM - 1)) return;

    const int z = blockIdx.z, zb = z / Hdiv, zh = z % Hdiv;
    Ah += (long long)zb*ab1 + (long long)zh*ab2;
    Al += (long long)zb*ab1 + (long long)zh*ab2;
    Bh += (long long)zb*bb1 + (long long)zh*bb2;
    Bl += (long long)zb*bb1 + (long long)zh*bb2;
    const long long coff = (long long)zb*cb1 + (long long)zh*cb2;

    extern __shared__ bf16 sm[];
    const uint32_t sbase = smem_u32(sm);

    const int tid = threadIdx.x;
    int Keff = K;
    if (kLimit) { int kl = m0 + BM; if (kl < Keff) Keff = kl; }
    const int nch = Keff >> 5;

    auto load_stage = [&](int st, int k0) {
        #pragma unroll
        for (int i = tid; i < BM * 4; i += 256) {
            int r = i >> 2, c8 = (i & 3) << 3;
            int gr = m0 + r;
            int ok = (gr < M) ? 16 : 0;
            if (gr >= M) gr = m0;
            size_t go = (size_t)gr * K + k0 + c8;
            uint32_t so = (uint32_t)((st * ASZ + r * LDS + c8) * 2);
            cpa16(sbase + so, Ah + go, ok);
            cpa16(sbase + so + 2 * ASZ * 2, Al + go, ok);
        }
        #pragma unroll
        for (int i = tid; i < BN * 4; i += 256) {
            int r = i >> 2, c8 = (i & 3) << 3;
            int gn = n0 + r;
            int ok = (gn < Nfull) ? 16 : 0;
            if (gn >= Nfull) gn = n0;
            size_t go = (size_t)gn * K + k0 + c8;
            uint32_t so = (uint32_t)((4 * ASZ + st * BSZ + r * LDS + c8) * 2);
            cpa16(sbase + so, Bh + go, ok);
            cpa16(sbase + so + 2 * BSZ * 2, Bl + go, ok);
        }
        asm volatile("cp.async.commit_group;" ::: "memory");
    };

    const int wid = tid >> 5, lane = tid & 31;
    const int wr = wid % WROWS, wc = wid / WROWS;
    const int wmBase = wr * WM, wnBase = wc * WN;

    float acc[MI][NI][4];
    #pragma unroll
    for (int mi = 0; mi < MI; mi++)
        #pragma unroll
        for (int ni = 0; ni < NI; ni++)
            #pragma unroll
            for (int j = 0; j < 4; j++) acc[mi][ni][j] = 0.f;

    load_stage(0, 0);

    for (int ch = 0; ch < nch; ch++) {
        if (ch + 1 < nch) {
            load_stage((ch + 1) & 1, (ch + 1) << 5);
            asm volatile("cp.async.wait_group 1;" ::: "memory");
        } else {
            asm volatile("cp.async.wait_group 0;" ::: "memory");
        }
        __syncthreads();

        const int st = ch & 1;
        const uint32_t aHb = sbase + (uint32_t)(st * ASZ * 2);
        const uint32_t aLb = aHb + (uint32_t)(2 * ASZ * 2);
        const uint32_t bHb = sbase + (uint32_t)((4 * ASZ + st * BSZ) * 2);
        const uint32_t bLb = bHb + (uint32_t)(2 * BSZ * 2);

        #pragma unroll
        for (int kk = 0; kk < 2; kk++) {
            const int colOff = kk * 16 + ((lane >> 4) << 3);
            uint32_t afH[MI][4], afL[MI][4];
            #pragma unroll
            for (int mi = 0; mi < MI; mi++) {
                uint32_t off = (uint32_t)(((wmBase + mi * 16 + (lane & 15)) * LDS + colOff) * 2);
                ldsm4(afH[mi], aHb + off);
                ldsm4(afL[mi], aLb + off);
            }
            #pragma unroll
            for (int nj = 0; nj < NI / 2; nj++) {
                uint32_t off = (uint32_t)(((wnBase + nj * 16 + (lane & 15)) * LDS + colOff) * 2);
                uint32_t bfH[4], bfL[4];
                ldsm4(bfH, bHb + off);
                ldsm4(bfL, bLb + off);
                #pragma unroll
                for (int mi = 0; mi < MI; mi++) {
                    mma_bf16(acc[mi][2*nj],   afH[mi], bfH[0], bfH[2]);
                    mma_bf16(acc[mi][2*nj],   afH[mi], bfL[0], bfL[2]);
                    mma_bf16(acc[mi][2*nj],   afL[mi], bfH[0], bfH[2]);
                    mma_bf16(acc[mi][2*nj+1], afH[mi], bfH[1], bfH[3]);
                    mma_bf16(acc[mi][2*nj+1], afH[mi], bfL[1], bfL[3]);
                    mma_bf16(acc[mi][2*nj+1], afL[mi], bfH[1], bfH[3]);
                }
            }
        }
        __syncthreads();
    }

    // epilogue
    const int g = lane >> 2, t4 = lane & 3;
    #pragma unroll
    for (int mi = 0; mi < MI; mi++) {
        #pragma unroll
        for (int ni = 0; ni < NI; ni++) {
            int col = n0 + wnBase + ni * 8 + t4 * 2;
            if (col >= Nfull) continue;
            #pragma unroll
            for (int half = 0; half < 2; half++) {
                int row = m0 + wmBase + mi * 16 + g + half * 8;
                if (row >= M) continue;
                float v0 = acc[mi][ni][half * 2 + 0] * alpha;
                float v1 = acc[mi][ni][half * 2 + 1] * alpha;
                long long base = coff + (long long)row * ldc + col;
                if (bias) { v0 += bias[col]; v1 += bias[col + 1]; }
                if (res)  { v0 += res[base]; v1 += res[base + 1]; }
                if (relu) { v0 = fmaxf(v0, 0.f); v1 = fmaxf(v1, 0.f); }
                if (outF) *(float2*)(outF + base) = make_float2(v0, v1);
                if (outH) {
                    uint32_t lw;
                    uint32_t hw = pack_split(v0, v1, lw);
                    *(uint32_t*)(outH + base) = hw;
                    *(uint32_t*)(outL + base) = lw;
                }
            }
        }
    }
}

// ---------------- fused flash attention ----------------
// grid (BB*HH, TT/128); 256 threads; per-warp 16x64 row-owning tiles.
#define LDF 72
__global__ __launch_bounds__(256, 1)
void flash_attn_k(const bf16* __restrict__ qh, const bf16* __restrict__ ql,
                  const bf16* __restrict__ kh, const bf16* __restrict__ kl,
                  const bf16* __restrict__ vth, const bf16* __restrict__ vtl,
                  bf16* __restrict__ oh, bf16* __restrict__ ol)
{
    extern __shared__ bf16 sm[];
    const uint32_t sbase = smem_u32(sm);
    const int bh = blockIdx.x;
    const int rb = blockIdx.y;
    const int m0 = rb * 128;
    const int tid = threadIdx.x, wid = tid >> 5, lane = tid & 31;
    const int g = lane >> 2, t4 = lane & 3;

    // smem element offsets
    const uint32_t OQH = 0, OQL = 128*LDF, OPH = 2*128*LDF, OPL = 3*128*LDF;
    const uint32_t OKV = 4*128*LDF;              // + st*4*64*LDF
    const uint32_t KVS = 4*64*LDF;

    // ---- load Q tile (128 x 64, hi/lo) ----
    for (int i = tid; i < 128 * 8; i += 256) {
        int r = i >> 3, c = (i & 7) << 3;
        size_t go = ((size_t)bh * TT + m0 + r) * HD + c;
        cpa16(sbase + (OQH + r * LDF + c) * 2, qh + go, 16);
        cpa16(sbase + (OQL + r * LDF + c) * 2, ql + go, 16);
    }
    asm volatile("cp.async.commit_group;" ::: "memory");

    auto load_kv = [&](int st, int j0) {
        uint32_t base = OKV + (uint32_t)st * KVS;
        for (int i = tid; i < 64 * 8; i += 256) {
            int r = i >> 3, c = (i & 7) << 3;
            size_t gk = ((size_t)bh * TT + j0 + r) * HD + c;
            size_t gv = ((size_t)bh * HD + r) * TT + j0 + c;
            cpa16(sbase + (base            + r * LDF + c) * 2, kh  + gk, 16);
            cpa16(sbase + (base +   64*LDF + r * LDF + c) * 2, kl  + gk, 16);
            cpa16(sbase + (base + 2*64*LDF + r * LDF + c) * 2, vth + gv, 16);
            cpa16(sbase + (base + 3*64*LDF + r * LDF + c) * 2, vtl + gv, 16);
        }
        asm volatile("cp.async.commit_group;" ::: "memory");
    };

    const int ntiles = 2 * rb + 2;
    load_kv(0, 0);

    float oacc[8][4];
    #pragma unroll
    for (int ni = 0; ni < 8; ni++)
        #pragma unroll
        for (int j = 0; j < 4; j++) oacc[ni][j] = 0.f;
    float mrow[2] = { -1e30f, -1e30f };
    float lrow[2] = { 0.f, 0.f };

    const int row0 = m0 + wid * 16 + g;   // thread's rows: row0, row0+8

    for (int t = 0; t < ntiles; t++) {
        const int j0 = t << 6;
        if (t + 1 < ntiles) {
            load_kv((t + 1) & 1, j0 + 64);
            asm volatile("cp.async.wait_group 1;" ::: "memory");
        } else {
            asm volatile("cp.async.wait_group 0;" ::: "memory");
        }
        __syncthreads();

        const uint32_t kvb = OKV + (uint32_t)(t & 1) * KVS;
        const uint32_t kHb = sbase + kvb * 2;
        const uint32_t kLb = sbase + (kvb + 64*LDF) * 2;
        const uint32_t vHb = sbase + (kvb + 2*64*LDF) * 2;
        const uint32_t vLb = sbase + (kvb + 3*64*LDF) * 2;

        // ---- S = Q @ K^T (3-pass) ----
        float acc[8][4];
        #pragma unroll
        for (int ni = 0; ni < 8; ni++)
            #pragma unroll
            for (int j = 0; j < 4; j++) acc[ni][j] = 0.f;

        #pragma unroll
        for (int kk = 0; kk < 4; kk++) {
            const int colOff = kk * 16 + ((lane >> 4) << 3);
            uint32_t aH[4], aL[4];
            uint32_t aoff = (uint32_t)(((wid * 16 + (lane & 15)) * LDF + colOff) * 2);
            ldsm4(aH, sbase + (OQH * 2) + aoff);
            ldsm4(aL, sbase + (OQL * 2) + aoff);
            #pragma unroll
            for (int nj = 0; nj < 4; nj++) {
                uint32_t boff = (uint32_t)(((nj * 16 + (lane & 15)) * LDF + colOff) * 2);
                uint32_t bH[4], bL[4];
                ldsm4(bH, kHb + boff);
                ldsm4(bL, kLb + boff);
                mma_bf16(acc[2*nj],   aH, bH[0], bH[2]);
                mma_bf16(acc[2*nj],   aH, bL[0], bL[2]);
                mma_bf16(acc[2*nj],   aL, bH[0], bH[2]);
                mma_bf16(acc[2*nj+1], aH, bH[1], bH[3]);
                mma_bf16(acc[2*nj+1], aH, bL[1], bL[3]);
                mma_bf16(acc[2*nj+1], aL, bH[1], bH[3]);
            }
        }

        // ---- scale + causal mask ----
        #pragma unroll
        for (int ni = 0; ni < 8; ni++) {
            int colBase = j0 + ni * 8 + t4 * 2;
            #pragma unroll
            for (int j = 0; j < 4; j++) {
                int row = row0 + ((j >> 1) << 3);
                int col = colBase + (j & 1);
                float v = acc[ni][j] * 0.125f;
                acc[ni][j] = (col <= row) ? v : -1e30f;
            }
        }

        // ---- online softmax ----
        #pragma unroll
        for (int half = 0; half < 2; half++) {
            float mt = -1e30f;
            #pragma unroll
            for (int ni = 0; ni < 8; ni++) {
                mt = fmaxf(mt, acc[ni][half*2+0]);
                mt = fmaxf(mt, acc[ni][half*2+1]);
            }
            mt = fmaxf(mt, __shfl_xor_sync(0xffffffffu, mt, 1));
            mt = fmaxf(mt, __shfl_xor_sync(0xffffffffu, mt, 2));
            float mnew = fmaxf(mrow[half], mt);
            float scale = __expf(mrow[half] - mnew);
            mrow[half] = mnew;
            float sum = 0.f;
            #pragma unroll
            for (int ni = 0; ni < 8; ni++) {
                float e0 = __expf(acc[ni][half*2+0] - mnew);
                float e1 = __expf(acc[ni][half*2+1] - mnew);
                acc[ni][half*2+0] = e0;
                acc[ni][half*2+1] = e1;
                sum += e0 + e1;
            }
            sum += __shfl_xor_sync(0xffffffffu, sum, 1);
            sum += __shfl_xor_sync(0xffffffffu, sum, 2);
            lrow[half] = lrow[half] * scale + sum;
            #pragma unroll
            for (int ni = 0; ni < 8; ni++) {
                oacc[ni][half*2+0] *= scale;
                oacc[ni][half*2+1] *= scale;
            }
        }

        // ---- store P (split bf16) to smem ----
        #pragma unroll
        for (int ni = 0; ni < 8; ni++) {
            int col = ni * 8 + t4 * 2;
            #pragma unroll
            for (int half = 0; half < 2; half++) {
                int rloc = wid * 16 + g + half * 8;
                uint32_t lw;
                uint32_t hw = pack_split(acc[ni][half*2+0], acc[ni][half*2+1], lw);
                *(uint32_t*)((char*)sm + (OPH + rloc * LDF + col) * 2) = hw;
                *(uint32_t*)((char*)sm + (OPL + rloc * LDF + col) * 2) = lw;
            }
        }
        __syncthreads();

        // ---- O += P @ V^T (V stored [hd, t]) 3-pass ----
        #pragma unroll
        for (int kk = 0; kk < 4; kk++) {
            const int colOff = kk * 16 + ((lane >> 4) << 3);
            uint32_t aH[4], aL[4];
            uint32_t aoff = (uint32_t)(((wid * 16 + (lane & 15)) * LDF + colOff) * 2);
            ldsm4(aH, sbase + (OPH * 2) + aoff);
            ldsm4(aL, sbase + (OPL * 2) + aoff);
            #pragma unroll
            for (int nj = 0; nj < 4; nj++) {
                uint32_t boff = (uint32_t)(((nj * 16 + (lane & 15)) * LDF + colOff) * 2);
                uint32_t bH[4], bL[4];
                ldsm4(bH, vHb + boff);
                ldsm4(bL, vLb + boff);
                mma_bf16(oacc[2*nj],   aH, bH[0], bH[2]);
                mma_bf16(oacc[2*nj],   aH, bL[0], bL[2]);
                mma_bf16(oacc[2*nj],   aL, bH[0], bH[2]);
                mma_bf16(oacc[2*nj+1], aH, bH[1], bH[3]);
                mma_bf16(oacc[2*nj+1], aH, bL[1], bL[3]);
                mma_bf16(oacc[2*nj+1], aL, bH[1], bH[3]);
            }
        }
        __syncthreads();
    }

    // ---- normalize + write O as split bf16 into [b, t, h*64+d] ----
    const int b = bh >> 4, h = bh & 15;
    float inv0 = 1.f / lrow[0], inv1 = 1.f / lrow[1];
    #pragma unroll
    for (int ni = 0; ni < 8; ni++) {
        int d = ni * 8 + t4 * 2;
        #pragma unroll
        for (int half = 0; half < 2; half++) {
            int trow = m0 + wid * 16 + g + half * 8;
            float inv = half ? inv1 : inv0;
            size_t base = ((size_t)b * TT + trow) * CC + h * HD + d;
            uint32_t lw;
            uint32_t hw = pack_split(oacc[ni][half*2+0] * inv,
                                     oacc[ni][half*2+1] * inv, lw);
            *(uint32_t*)(oh + base) = hw;
            *(uint32_t*)(ol + base) = lw;
        }
    }
}

// ---------------- block reductions ----------------
__device__ __forceinline__ float blockReduceSum256(float v, float* sh) {
    #pragma unroll
    for (int o = 16; o > 0; o >>= 1) v += __shfl_xor_sync(0xffffffffu, v, o);
    int w = threadIdx.x >> 5;
    if ((threadIdx.x & 31) == 0) sh[w] = v;
    __syncthreads();
    if (threadIdx.x < 8) {
        v = sh[threadIdx.x];
        #pragma unroll
        for (int o = 4; o > 0; o >>= 1) v += __shfl_xor_sync(0xffu, v, o);
        if (threadIdx.x == 0) sh[0] = v;
    }
    __syncthreads();
    float r = sh[0]; __syncthreads(); return r;
}

__device__ __forceinline__ void split_store(bf16* H, bf16* L, size_t i, float v) {
    bf16 h = __float2bfloat16(v);
    H[i] = h;
    L[i] = __float2bfloat16(v - __bfloat162float(h));
}

// ---------------- layernorm -> split bf16 ----------------
__global__ __launch_bounds__(256)
void layernorm_split_k(const float* __restrict__ x, const float* __restrict__ g,
                       const float* __restrict__ b, bf16* __restrict__ oh, bf16* __restrict__ ol)
{
    __shared__ float sh[8];
    const size_t row = blockIdx.x;
    const float* xr = x + row * CC;
    const int c = threadIdx.x * 4;
    float4 xv = *(const float4*)(xr + c);
    float s  = xv.x + xv.y + xv.z + xv.w;
    float ss = xv.x*xv.x + xv.y*xv.y + xv.z*xv.z + xv.w*xv.w;
    s = blockReduceSum256(s, sh);
    ss = blockReduceSum256(ss, sh);
    float mean = s * (1.f / CC);
    float var = ss * (1.f / CC) - mean * mean;
    float inv = rsqrtf(var + 1e-5f);
    float4 gv = *(const float4*)(g + c);
    float4 bv = *(const float4*)(b + c);
    size_t base = row * CC + c;
    split_store(oh, ol, base + 0, (xv.x - mean) * inv * gv.x + bv.x);
    split_store(oh, ol, base + 1, (xv.y - mean) * inv * gv.y + bv.y);
    split_store(oh, ol, base + 2, (xv.z - mean) * inv * gv.z + bv.z);
    split_store(oh, ol, base + 3, (xv.w - mean) * inv * gv.w + bv.w);
}

// ---------------- repack fused qkv -> q,k [B,H,T,HD] split; v -> [B,H,HD,T] split ----------------
__global__ __launch_bounds__(256)
void repack_qkv_k(const float* __restrict__ qkv,
                  bf16* qh, bf16* ql, bf16* kh, bf16* kl, bf16* vth, bf16* vtl)
{
    size_t idx = (size_t)blockIdx.x * 256 + threadIdx.x;
    int c3 = idx % (3 * CC);
    size_t bt = idx / (3 * CC);
    int t = bt & 1023;
    int b = bt >> 10;
    int which = c3 >> 10;
    int c = c3 & 1023;
    int h = c >> 6, d = c & 63;
    float v = qkv[idx];
    if (which == 0) {
        size_t o1 = (((size_t)(b * HH + h)) * TT + t) * HD + d;
        split_store(qh, ql, o1, v);
    } else if (which == 1) {
        size_t o1 = (((size_t)(b * HH + h)) * TT + t) * HD + d;
        split_store(kh, kl, o1, v);
    } else {
        size_t o2 = (((size_t)(b * HH + h)) * HD + d) * TT + t;
        split_store(vth, vtl, o2, v);
    }
}

// ---------------- weight transpose + split ----------------
__global__ void transpose_split_k(const float* __restrict__ W, bf16* __restrict__ hi,
                                  bf16* __restrict__ lo, int K, int N, long long zOutStride)
{
    __shared__ float t[32][33];
    W  += (size_t)blockIdx.z * K * N;
    hi += (size_t)blockIdx.z * zOutStride;
    lo += (size_t)blockIdx.z * zOutStride;
    int k0 = blockIdx.y * 32, n0 = blockIdx.x * 32;
    int tx = threadIdx.x, ty = threadIdx.y;
    #pragma unroll
    for (int i = 0; i < 32; i += 8)
        t[ty + i][tx] = W[(size_t)(k0 + ty + i) * N + n0 + tx];
    __syncthreads();
    #pragma unroll
    for (int i = 0; i < 32; i += 8)
        split_store(hi, lo, (size_t)(n0 + ty + i) * K + k0 + tx, t[tx][ty + i]);
}

// ---------------- elementwise split ----------------
__global__ void split_k(const float* __restrict__ W, bf16* hi, bf16* lo, int n)
{
    int idx = blockIdx.x * 256 + threadIdx.x;
    if (idx < n) split_store(hi, lo, idx, W[idx]);
}

// ---------------- im2col + split ----------------
__global__ void im2col_split_k(const float* __restrict__ img, bf16* hi, bf16* lo)
{
    int idx = blockIdx.x * 256 + threadIdx.x;
    if (idx >= BB * NPATCH * KIM) return;
    int k = idx % KIM;
    int bn = idx / KIM;
    int n = bn % NPATCH;
    int b = bn / NPATCH;
    int ci = k >> 8;
    int rr = k & 255;
    int kh = rr >> 4;
    int kw = rr & 15;
    int ph = n / 21, pw = n % 21;
    float v = img[(((size_t)b * 3 + ci) * IMG + ph * PATCH + kh) * IMG + pw * PATCH + kw];
    split_store(hi, lo, idx, v);
}

// ---------------- embedding assembly ----------------
__global__ __launch_bounds__(256)
void embed_k(const int* __restrict__ toks, const float* __restrict__ tok_emb,
             const float* __restrict__ txt_pos, const float* __restrict__ img_pos,
             const float* __restrict__ p, float* __restrict__ x)
{
    const int bt = blockIdx.x;
    const int b = bt >> 10;
    const int t = bt & 1023;
    const int c = threadIdx.x * 4;
    const float* src;
    const float* extra = nullptr;
    if (t == 0)      src = tok_emb + 1 * CC;
    else if (t == 1) src = tok_emb + 8 * CC;
    else if (t < 443) {
        int n = t - 2;
        src = p + ((size_t)(b * NPATCH + n)) * CC;
        extra = img_pos + (size_t)n * CC;
    }
    else if (t == 443) src = tok_emb + 9 * CC;
    else {
        int tok = toks[b * TTXT + (t - 444)];
        src = tok_emb + (size_t)tok * CC;
    }
    float4 v = *(const float4*)(src + c);
    float4 tp = *(const float4*)(txt_pos + (size_t)t * CC + c);
    v.x += tp.x; v.y += tp.y; v.z += tp.z; v.w += tp.w;
    if (extra) {
        float4 e = *(const float4*)(extra + c);
        v.x += e.x; v.y += e.y; v.z += e.z; v.w += e.w;
    }
    *(float4*)(x + (size_t)bt * CC + c) = v;
}

// ---------------- host-side GEMM launcher ----------------
static inline void tc(const bf16* Ah, const bf16* Al, const bf16* Bh, const bf16* Bl,
                      const float* bias, const float* res,
                      float* outF, bf16* outH, bf16* outL,
                      int M, int N, int K, int ldc,
                      float alpha = 1.f, int relu = 0)
{
    dim3 grid((N + 127) / 128, (M + 127) / 128, 1);
    size_t sh = (size_t)(4 * 128 * LDS + 4 * 128 * LDS) * 2;
    gemm_mma<128, 4, 2><<<grid, 256, sh>>>(Ah, Al, Bh, Bl, bias, res, outF, outH, outL,
        M, N, K, ldc, 0, 0, 0, 0, 0, 0, 1, alpha, relu, 0, 0);
}

#define SYM(name) ({ void* _p; cudaGetSymbolAddress(&_p, name); _p; })

extern "C" void kernel_launch(void* const* d_in, const int* in_sizes, int n_in,
                              void* d_out, int out_size)
{
    const int*   text_tokens = (const int*)  d_in[0];
    const float* images      = (const float*)d_in[1];
    const float* tok_emb     = (const float*)d_in[2];
    const float* txt_pos     = (const float*)d_in[3];
    const float* img_pos     = (const float*)d_in[4];
    const float* patch_w     = (const float*)d_in[5];
    const float* patch_b     = (const float*)d_in[6];
    const float* ln1_g       = (const float*)d_in[7];
    const float* ln1_b       = (const float*)d_in[8];
    const float* wq          = (const float*)d_in[9];
    const float* wk          = (const float*)d_in[10];
    const float* wv          = (const float*)d_in[11];
    const float* wo          = (const float*)d_in[12];
    const float* bo          = (const float*)d_in[13];
    const float* ln2_g       = (const float*)d_in[14];
    const float* ln2_b       = (const float*)d_in[15];
    const float* w1          = (const float*)d_in[16];
    const float* b1          = (const float*)d_in[17];
    const float* w2          = (const float*)d_in[18];
    const float* b2          = (const float*)d_in[19];
    const float* lnf_g       = (const float*)d_in[20];
    const float* lnf_b       = (const float*)d_in[21];
    const float* lm_w        = (const float*)d_in[22];
    const float* lm_b        = (const float*)d_in[23];
    float* out = (float*)d_out;

    cudaFuncSetAttribute(gemm_mma<128, 4, 2>, cudaFuncAttributeMaxDynamicSharedMemorySize,
                         (4 * 128 * LDS + 4 * 128 * LDS) * 2);
    const int FLASH_SMEM = (4 * 128 * LDF + 2 * 4 * 64 * LDF) * 2;
    cudaFuncSetAttribute(flash_attn_k, cudaFuncAttributeMaxDynamicSharedMemorySize,
                         FLASH_SMEM);

    float* px   = (float*)SYM(g_x);
    float* pqkv = (float*)SYM(g_qkv);
    float* ppp  = (float*)SYM(g_pp);
    bf16 *pqh = (bf16*)SYM(g_qh), *pql = (bf16*)SYM(g_ql);
    bf16 *pkh = (bf16*)SYM(g_kh), *pkl = (bf16*)SYM(g_kl);
    bf16 *pvth = (bf16*)SYM(g_vth), *pvtl = (bf16*)SYM(g_vtl);
    bf16 *pah = (bf16*)SYM(g_ah), *pal = (bf16*)SYM(g_al);
    bf16 *pfh = (bf16*)SYM(g_fh), *pfl = (bf16*)SYM(g_fl);
    bf16 *pwqkvh = (bf16*)SYM(g_wqkvh), *pwqkvl = (bf16*)SYM(g_wqkvl);
    bf16 *pwoh = (bf16*)SYM(g_woh), *pwol = (bf16*)SYM(g_wol);
    bf16 *pw1h = (bf16*)SYM(g_w1h), *pw1l = (bf16*)SYM(g_w1l);
    bf16 *pw2h = (bf16*)SYM(g_w2h), *pw2l = (bf16*)SYM(g_w2l);
    bf16 *plmh = (bf16*)SYM(g_lmh), *plml = (bf16*)SYM(g_lml);
    bf16 *ppwh = (bf16*)SYM(g_pwh), *ppwl = (bf16*)SYM(g_pwl);
    bf16 *pimh = (bf16*)SYM(g_imh), *piml = (bf16*)SYM(g_iml);

    // ---- weight prep: transpose + split (q,k,v fused into [3C, C] per layer) ----
    dim3 tb(32, 8);
    const long long QKV_Z = (long long)3 * CC * CC;
    transpose_split_k<<<dim3(CC/32,  CC/32,  LL), tb>>>(wq, pwqkvh,            pwqkvl,            CC, CC, QKV_Z);
    transpose_split_k<<<dim3(CC/32,  CC/32,  LL), tb>>>(wk, pwqkvh + CC*CC,    pwqkvl + CC*CC,    CC, CC, QKV_Z);
    transpose_split_k<<<dim3(CC/32,  CC/32,  LL), tb>>>(wv, pwqkvh + 2*CC*CC,  pwqkvl + 2*CC*CC,  CC, CC, QKV_Z);
    transpose_split_k<<<dim3(CC/32,  CC/32,  LL), tb>>>(wo, pwoh, pwol, CC, CC, (long long)CC*CC);
    transpose_split_k<<<dim3(FF_/32, CC/32,  LL), tb>>>(w1, pw1h, pw1l, CC, FF_, (long long)CC*FF_);
    transpose_split_k<<<dim3(CC/32,  FF_/32, LL), tb>>>(w2, pw2h, pw2l, FF_, CC, (long long)CC*FF_);
    transpose_split_k<<<dim3(VV/32,  CC/32,  1),  tb>>>(lm_w, plmh, plml, CC, VV, 0);
    split_k<<<(CC*KIM + 255)/256, 256>>>(patch_w, ppwh, ppwl, CC*KIM);

    // ---- patch embedding ----
    im2col_split_k<<<(BB*NPATCH*KIM + 255)/256, 256>>>(images, pimh, piml);
    tc(pimh, piml, ppwh, ppwl, patch_b, nullptr, ppp, nullptr, nullptr,
       BB*NPATCH, CC, KIM, CC);

    // ---- embedding assembly ----
    embed_k<<<BB*TT, 256>>>(text_tokens, tok_emb, txt_pos, img_pos, ppp, px);

    const int M = MTOK;
    for (int l = 0; l < LL; l++) {
        size_t wOff = (size_t)l * CC * CC, w1Off = (size_t)l * CC * FF_;
        size_t qkvOff = (size_t)l * 3 * CC * CC;

        layernorm_split_k<<<M, 256>>>(px, ln1_g + l*CC, ln1_b + l*CC, pah, pal);

        // fused q|k|v projection: [M, 3C]
        tc(pah, pal, pwqkvh + qkvOff, pwqkvl + qkvOff, nullptr, nullptr,
           pqkv, nullptr, nullptr, M, 3*CC, CC, 3*CC);

        repack_qkv_k<<<M*3*CC/256, 256>>>(pqkv, pqh, pql, pkh, pkl, pvth, pvtl);

        // fused flash attention -> split bf16 at [b,t,h,d]
        flash_attn_k<<<dim3(BB*HH, TT/128), 256, FLASH_SMEM>>>(
            pqh, pql, pkh, pkl, pvth, pvtl, pah, pal);

        // out proj + bias + residual -> x
        tc(pah, pal, pwoh + wOff, pwol + wOff, bo + l*CC, px, px, nullptr, nullptr,
           M, CC, CC, CC);

        layernorm_split_k<<<M, 256>>>(px, ln2_g + l*CC, ln2_b + l*CC, pah, pal);

        // ffn
        tc(pah, pal, pw1h + w1Off, pw1l + w1Off, b1 + l*FF_, nullptr,
           nullptr, pfh, pfl, M, FF_, CC, FF_, 1.f, /*relu*/1);
        tc(pfh, pfl, pw2h + w1Off, pw2l + w1Off, b2 + l*CC, px, px, nullptr, nullptr,
           M, CC, FF_, CC);
    }

    // ---- final LN + LM head ----
    layernorm_split_k<<<M, 256>>>(px, lnf_g, lnf_b, pah, pal);
    tc(pah, pal, plmh, plml, lm_b, nullptr, out, nullptr, nullptr,
       M, VV, CC, VV);
}

// round 6
// speedup vs baseline: 3.3217x; 1.0527x over previous
#include <cuda_runtime.h>
#include <cuda_bf16.h>
#include <cstdint>

typedef __nv_bfloat16 bf16;

// ---------------- problem constants ----------------
#define BB    4
#define TT    1024
#define CC    1024
#define HH    16
#define HD    64
#define LL    6
#define VV    16000
#define FF_   4096
#define TTXT  580
#define NPATCH 441
#define KIM   768
#define IMG   336
#define PATCH 16
#define MTOK  (BB*TT)          // 4096

// ---------------- scratch (device globals; no allocation) ----------------
__device__ float g_x  [(size_t)MTOK*CC];
__device__ float g_pp [(size_t)BB*NPATCH*CC];

__device__ bf16 g_qh[(size_t)MTOK*CC], g_ql[(size_t)MTOK*CC];
__device__ bf16 g_kh[(size_t)MTOK*CC], g_kl[(size_t)MTOK*CC];
__device__ bf16 g_vth[(size_t)MTOK*CC], g_vtl[(size_t)MTOK*CC];
__device__ bf16 g_ah[(size_t)MTOK*CC], g_al[(size_t)MTOK*CC];
__device__ bf16 g_fh[(size_t)MTOK*FF_], g_fl[(size_t)MTOK*FF_];

__device__ bf16 g_wqkvh[(size_t)LL*3*CC*CC], g_wqkvl[(size_t)LL*3*CC*CC];
__device__ bf16 g_woh[(size_t)LL*CC*CC], g_wol[(size_t)LL*CC*CC];
__device__ bf16 g_w1h[(size_t)LL*CC*FF_], g_w1l[(size_t)LL*CC*FF_];
__device__ bf16 g_w2h[(size_t)LL*CC*FF_], g_w2l[(size_t)LL*CC*FF_];
__device__ bf16 g_lmh[(size_t)CC*VV],    g_lml[(size_t)CC*VV];
__device__ bf16 g_pwh[(size_t)CC*KIM],   g_pwl[(size_t)CC*KIM];
__device__ bf16 g_imh[(size_t)BB*NPATCH*KIM], g_iml[(size_t)BB*NPATCH*KIM];

// ---------------- low-level helpers ----------------
__device__ __forceinline__ uint32_t smem_u32(const void* p) {
    uint32_t a;
    asm("{ .reg .u64 t; cvta.to.shared.u64 t, %1; cvt.u32.u64 %0, t; }" : "=r"(a) : "l"(p));
    return a;
}
__device__ __forceinline__ void cpa16(uint32_t dst, const void* src, int szbytes) {
    asm volatile("cp.async.cg.shared.global [%0], [%1], 16, %2;"
                 :: "r"(dst), "l"(src), "r"(szbytes) : "memory");
}
__device__ __forceinline__ void ldsm4(uint32_t (&r)[4], uint32_t addr) {
    asm volatile("ldmatrix.sync.aligned.m8n8.x4.shared.b16 {%0,%1,%2,%3}, [%4];"
                 : "=r"(r[0]), "=r"(r[1]), "=r"(r[2]), "=r"(r[3]) : "r"(addr));
}
__device__ __forceinline__ void mma_bf16(float (&d)[4], const uint32_t (&a)[4],
                                         uint32_t b0, uint32_t b1) {
    asm volatile("mma.sync.aligned.m16n8k16.row.col.f32.bf16.bf16.f32 "
                 "{%0,%1,%2,%3}, {%4,%5,%6,%7}, {%8,%9}, {%0,%1,%2,%3};"
                 : "+f"(d[0]), "+f"(d[1]), "+f"(d[2]), "+f"(d[3])
                 : "r"(a[0]), "r"(a[1]), "r"(a[2]), "r"(a[3]), "r"(b0), "r"(b1));
}
__device__ __forceinline__ uint32_t pack_split(float v0, float v1, uint32_t& lw) {
    bf16 h0 = __float2bfloat16(v0), h1 = __float2bfloat16(v1);
    float r0 = v0 - __bfloat162float(h0), r1 = v1 - __bfloat162float(h1);
    bf16 l0 = __float2bfloat16(r0), l1 = __float2bfloat16(r1);
    lw = (uint32_t)__bfloat16_as_ushort(l0) | ((uint32_t)__bfloat16_as_ushort(l1) << 16);
    return (uint32_t)__bfloat16_as_ushort(h0) | ((uint32_t)__bfloat16_as_ushort(h1) << 16);
}

// ---------------- split-bf16 tensor-core GEMM (mma.sync) ----------------
#define LDS 40
#define BM  128

// outMode: 0 = normal (outF / outH+outL with bias/res/relu)
//          1 = QKV scatter: write split q,k at [b,h,t,d] and vt at [b,h,d,t]
__global__ __launch_bounds__(256, 2)
void gemm_mma(const bf16* __restrict__ Ah, const bf16* __restrict__ Al,
              const bf16* __restrict__ Bh, const bf16* __restrict__ Bl,
              const float* __restrict__ bias, const float* __restrict__ res,
              float* __restrict__ outF, bf16* __restrict__ outH, bf16* __restrict__ outL,
              bf16* __restrict__ okh, bf16* __restrict__ okl,
              bf16* __restrict__ ovh, bf16* __restrict__ ovl,
              int M, int Nfull, int K, int ldc,
              float alpha, int relu, int outMode)
{
    constexpr int WROWS = 4, WCOLS = 2, BN = 128;
    constexpr int WM = BM / WROWS;       // 32
    constexpr int WN = BN / WCOLS;       // 64
    constexpr int MI = WM / 16;          // 2
    constexpr int NI = WN / 8;           // 8
    constexpr int ASZ = BM * LDS;
    constexpr int BSZ = BN * LDS;

    const int m0 = blockIdx.y * BM;
    const int n0 = blockIdx.x * BN;

    extern __shared__ bf16 sm[];
    const uint32_t sbase = smem_u32(sm);

    const int tid = threadIdx.x;
    const int nch = K >> 5;

    auto load_stage = [&](int st, int k0) {
        #pragma unroll
        for (int i = tid; i < BM * 4; i += 256) {
            int r = i >> 2, c8 = (i & 3) << 3;
            int gr = m0 + r;
            int ok = (gr < M) ? 16 : 0;
            if (gr >= M) gr = m0;
            size_t go = (size_t)gr * K + k0 + c8;
            uint32_t so = (uint32_t)((st * ASZ + r * LDS + c8) * 2);
            cpa16(sbase + so, Ah + go, ok);
            cpa16(sbase + so + 2 * ASZ * 2, Al + go, ok);
        }
        #pragma unroll
        for (int i = tid; i < BN * 4; i += 256) {
            int r = i >> 2, c8 = (i & 3) << 3;
            int gn = n0 + r;
            int ok = (gn < Nfull) ? 16 : 0;
            if (gn >= Nfull) gn = n0;
            size_t go = (size_t)gn * K + k0 + c8;
            uint32_t so = (uint32_t)((4 * ASZ + st * BSZ + r * LDS + c8) * 2);
            cpa16(sbase + so, Bh + go, ok);
            cpa16(sbase + so + 2 * BSZ * 2, Bl + go, ok);
        }
        asm volatile("cp.async.commit_group;" ::: "memory");
    };

    const int wid = tid >> 5, lane = tid & 31;
    const int wr = wid % WROWS, wc = wid / WROWS;
    const int wmBase = wr * WM, wnBase = wc * WN;

    float acc[MI][NI][4];
    #pragma unroll
    for (int mi = 0; mi < MI; mi++)
        #pragma unroll
        for (int ni = 0; ni < NI; ni++)
            #pragma unroll
            for (int j = 0; j < 4; j++) acc[mi][ni][j] = 0.f;

    load_stage(0, 0);

    for (int ch = 0; ch < nch; ch++) {
        if (ch + 1 < nch) {
            load_stage((ch + 1) & 1, (ch + 1) << 5);
            asm volatile("cp.async.wait_group 1;" ::: "memory");
        } else {
            asm volatile("cp.async.wait_group 0;" ::: "memory");
        }
        __syncthreads();

        const int st = ch & 1;
        const uint32_t aHb = sbase + (uint32_t)(st * ASZ * 2);
        const uint32_t aLb = aHb + (uint32_t)(2 * ASZ * 2);
        const uint32_t bHb = sbase + (uint32_t)((4 * ASZ + st * BSZ) * 2);
        const uint32_t bLb = bHb + (uint32_t)(2 * BSZ * 2);

        #pragma unroll
        for (int kk = 0; kk < 2; kk++) {
            const int colOff = kk * 16 + ((lane >> 4) << 3);
            uint32_t afH[MI][4], afL[MI][4];
            #pragma unroll
            for (int mi = 0; mi < MI; mi++) {
                uint32_t off = (uint32_t)(((wmBase + mi * 16 + (lane & 15)) * LDS + colOff) * 2);
                ldsm4(afH[mi], aHb + off);
                ldsm4(afL[mi], aLb + off);
            }
            #pragma unroll
            for (int nj = 0; nj < NI / 2; nj++) {
                uint32_t off = (uint32_t)(((wnBase + nj * 16 + (lane & 15)) * LDS + colOff) * 2);
                uint32_t bfH[4], bfL[4];
                ldsm4(bfH, bHb + off);
                ldsm4(bfL, bLb + off);
                // pass-interleaved: same-acc reuse distance = 4
                #pragma unroll
                for (int mi = 0; mi < MI; mi++) {
                    mma_bf16(acc[mi][2*nj],   afH[mi], bfH[0], bfH[2]);
                    mma_bf16(acc[mi][2*nj+1], afH[mi], bfH[1], bfH[3]);
                }
                #pragma unroll
                for (int mi = 0; mi < MI; mi++) {
                    mma_bf16(acc[mi][2*nj],   afH[mi], bfL[0], bfL[2]);
                    mma_bf16(acc[mi][2*nj+1], afH[mi], bfL[1], bfL[3]);
                }
                #pragma unroll
                for (int mi = 0; mi < MI; mi++) {
                    mma_bf16(acc[mi][2*nj],   afL[mi], bfH[0], bfH[2]);
                    mma_bf16(acc[mi][2*nj+1], afL[mi], bfH[1], bfH[3]);
                }
            }
        }
        __syncthreads();
    }

    // epilogue
    const int g = lane >> 2, t4 = lane & 3;
    #pragma unroll
    for (int mi = 0; mi < MI; mi++) {
        #pragma unroll
        for (int ni = 0; ni < NI; ni++) {
            int col = n0 + wnBase + ni * 8 + t4 * 2;
            if (col >= Nfull) continue;
            #pragma unroll
            for (int half = 0; half < 2; half++) {
                int row = m0 + wmBase + mi * 16 + g + half * 8;
                if (row >= M) continue;
                float v0 = acc[mi][ni][half * 2 + 0] * alpha;
                float v1 = acc[mi][ni][half * 2 + 1] * alpha;
                if (outMode == 1) {
                    // QKV scatter
                    int which = col >> 10;
                    int c = col & 1023;
                    int h = c >> 6, d = c & 63;
                    int b = row >> 10, t = row & 1023;
                    uint32_t lw;
                    uint32_t hw = pack_split(v0, v1, lw);
                    if (which < 2) {
                        size_t base = (((size_t)(b * HH + h)) * TT + t) * HD + d;
                        bf16* H = which ? okh : outH;
                        bf16* L = which ? okl : outL;
                        *(uint32_t*)(H + base) = hw;
                        *(uint32_t*)(L + base) = lw;
                    } else {
                        size_t vb = (((size_t)(b * HH + h)) * HD + d) * TT + t;
                        ovh[vb]      = __ushort_as_bfloat16((unsigned short)(hw & 0xffff));
                        ovh[vb + TT] = __ushort_as_bfloat16((unsigned short)(hw >> 16));
                        ovl[vb]      = __ushort_as_bfloat16((unsigned short)(lw & 0xffff));
                        ovl[vb + TT] = __ushort_as_bfloat16((unsigned short)(lw >> 16));
                    }
                } else {
                    long long base = (long long)row * ldc + col;
                    if (bias) { v0 += bias[col]; v1 += bias[col + 1]; }
                    if (res)  { v0 += res[base]; v1 += res[base + 1]; }
                    if (relu) { v0 = fmaxf(v0, 0.f); v1 = fmaxf(v1, 0.f); }
                    if (outF) *(float2*)(outF + base) = make_float2(v0, v1);
                    if (outH) {
                        uint32_t lw;
                        uint32_t hw = pack_split(v0, v1, lw);
                        *(uint32_t*)(outH + base) = hw;
                        *(uint32_t*)(outL + base) = lw;
                    }
                }
            }
        }
    }
}

// ---------------- fused flash attention (register-P, 2 CTA/SM) ----------------
#define LDF 72
__global__ __launch_bounds__(256, 2)
void flash_attn_k(const bf16* __restrict__ qh, const bf16* __restrict__ ql,
                  const bf16* __restrict__ kh, const bf16* __restrict__ kl,
                  const bf16* __restrict__ vth, const bf16* __restrict__ vtl,
                  bf16* __restrict__ oh, bf16* __restrict__ ol)
{
    extern __shared__ bf16 sm[];
    const uint32_t sbase = smem_u32(sm);
    const int id = blockIdx.x;
    const int rb = id & 7;           // interleaved for wave balance
    const int bh = id >> 3;
    const int m0 = rb * 128;
    const int tid = threadIdx.x, wid = tid >> 5, lane = tid & 31;
    const int g = lane >> 2, t4 = lane & 3;

    const uint32_t OQH = 0, OQL = 128*LDF;
    const uint32_t OKV = 2*128*LDF;
    const uint32_t KVS = 4*64*LDF;

    // ---- load Q tile (128 x 64, hi/lo) ----
    for (int i = tid; i < 128 * 8; i += 256) {
        int r = i >> 3, c = (i & 7) << 3;
        size_t go = ((size_t)bh * TT + m0 + r) * HD + c;
        cpa16(sbase + (OQH + r * LDF + c) * 2, qh + go, 16);
        cpa16(sbase + (OQL + r * LDF + c) * 2, ql + go, 16);
    }
    asm volatile("cp.async.commit_group;" ::: "memory");

    auto load_kv = [&](int st, int j0) {
        uint32_t base = OKV + (uint32_t)st * KVS;
        for (int i = tid; i < 64 * 8; i += 256) {
            int r = i >> 3, c = (i & 7) << 3;
            size_t gk = ((size_t)bh * TT + j0 + r) * HD + c;
            size_t gv = ((size_t)bh * HD + r) * TT + j0 + c;
            cpa16(sbase + (base            + r * LDF + c) * 2, kh  + gk, 16);
            cpa16(sbase + (base +   64*LDF + r * LDF + c) * 2, kl  + gk, 16);
            cpa16(sbase + (base + 2*64*LDF + r * LDF + c) * 2, vth + gv, 16);
            cpa16(sbase + (base + 3*64*LDF + r * LDF + c) * 2, vtl + gv, 16);
        }
        asm volatile("cp.async.commit_group;" ::: "memory");
    };

    const int ntiles = 2 * rb + 2;
    load_kv(0, 0);

    float oacc[8][4];
    #pragma unroll
    for (int ni = 0; ni < 8; ni++)
        #pragma unroll
        for (int j = 0; j < 4; j++) oacc[ni][j] = 0.f;
    float mrow[2] = { -1e30f, -1e30f };
    float lrow[2] = { 0.f, 0.f };

    const int row0 = m0 + wid * 16 + g;

    for (int t = 0; t < ntiles; t++) {
        const int j0 = t << 6;
        if (t + 1 < ntiles) {
            load_kv((t + 1) & 1, j0 + 64);
            asm volatile("cp.async.wait_group 1;" ::: "memory");
        } else {
            asm volatile("cp.async.wait_group 0;" ::: "memory");
        }
        __syncthreads();

        const uint32_t kvb = OKV + (uint32_t)(t & 1) * KVS;
        const uint32_t kHb = sbase + kvb * 2;
        const uint32_t kLb = sbase + (kvb + 64*LDF) * 2;
        const uint32_t vHb = sbase + (kvb + 2*64*LDF) * 2;
        const uint32_t vLb = sbase + (kvb + 3*64*LDF) * 2;

        // ---- S = Q @ K^T (3-pass) ----
        float acc[8][4];
        #pragma unroll
        for (int ni = 0; ni < 8; ni++)
            #pragma unroll
            for (int j = 0; j < 4; j++) acc[ni][j] = 0.f;

        #pragma unroll
        for (int kk = 0; kk < 4; kk++) {
            const int colOff = kk * 16 + ((lane >> 4) << 3);
            uint32_t aH[4], aL[4];
            uint32_t aoff = (uint32_t)(((wid * 16 + (lane & 15)) * LDF + colOff) * 2);
            ldsm4(aH, sbase + (OQH * 2) + aoff);
            ldsm4(aL, sbase + (OQL * 2) + aoff);
            #pragma unroll
            for (int nj = 0; nj < 4; nj++) {
                uint32_t boff = (uint32_t)(((nj * 16 + (lane & 15)) * LDF + colOff) * 2);
                uint32_t bH[4], bL[4];
                ldsm4(bH, kHb + boff);
                ldsm4(bL, kLb + boff);
                mma_bf16(acc[2*nj],   aH, bH[0], bH[2]);
                mma_bf16(acc[2*nj+1], aH, bH[1], bH[3]);
                mma_bf16(acc[2*nj],   aH, bL[0], bL[2]);
                mma_bf16(acc[2*nj+1], aH, bL[1], bL[3]);
                mma_bf16(acc[2*nj],   aL, bH[0], bH[2]);
                mma_bf16(acc[2*nj+1], aL, bH[1], bH[3]);
            }
        }

        // ---- scale + causal mask ----
        #pragma unroll
        for (int ni = 0; ni < 8; ni++) {
            int colBase = j0 + ni * 8 + t4 * 2;
            #pragma unroll
            for (int j = 0; j < 4; j++) {
                int row = row0 + ((j >> 1) << 3);
                int col = colBase + (j & 1);
                float v = acc[ni][j] * 0.125f;
                acc[ni][j] = (col <= row) ? v : -1e30f;
            }
        }

        // ---- online softmax ----
        #pragma unroll
        for (int half = 0; half < 2; half++) {
            float mt = -1e30f;
            #pragma unroll
            for (int ni = 0; ni < 8; ni++) {
                mt = fmaxf(mt, acc[ni][half*2+0]);
                mt = fmaxf(mt, acc[ni][half*2+1]);
            }
            mt = fmaxf(mt, __shfl_xor_sync(0xffffffffu, mt, 1));
            mt = fmaxf(mt, __shfl_xor_sync(0xffffffffu, mt, 2));
            float mnew = fmaxf(mrow[half], mt);
            float scale = __expf(mrow[half] - mnew);
            mrow[half] = mnew;
            float sum = 0.f;
            #pragma unroll
            for (int ni = 0; ni < 8; ni++) {
                float e0 = __expf(acc[ni][half*2+0] - mnew);
                float e1 = __expf(acc[ni][half*2+1] - mnew);
                acc[ni][half*2+0] = e0;
                acc[ni][half*2+1] = e1;
                sum += e0 + e1;
            }
            sum += __shfl_xor_sync(0xffffffffu, sum, 1);
            sum += __shfl_xor_sync(0xffffffffu, sum, 2);
            lrow[half] = lrow[half] * scale + sum;
            #pragma unroll
            for (int ni = 0; ni < 8; ni++) {
                oacc[ni][half*2+0] *= scale;
                oacc[ni][half*2+1] *= scale;
            }
        }

        // ---- O += P @ V^T : P converted to A-fragments in registers ----
        #pragma unroll
        for (int kk = 0; kk < 4; kk++) {
            uint32_t aH[4], aL[4];
            aH[0] = pack_split(acc[2*kk][0],   acc[2*kk][1],   aL[0]);
            aH[1] = pack_split(acc[2*kk][2],   acc[2*kk][3],   aL[1]);
            aH[2] = pack_split(acc[2*kk+1][0], acc[2*kk+1][1], aL[2]);
            aH[3] = pack_split(acc[2*kk+1][2], acc[2*kk+1][3], aL[3]);
            const int colOff = kk * 16 + ((lane >> 4) << 3);
            #pragma unroll
            for (int nj = 0; nj < 4; nj++) {
                uint32_t boff = (uint32_t)(((nj * 16 + (lane & 15)) * LDF + colOff) * 2);
                uint32_t bH[4], bL[4];
                ldsm4(bH, vHb + boff);
                ldsm4(bL, vLb + boff);
                mma_bf16(oacc[2*nj],   aH, bH[0], bH[2]);
                mma_bf16(oacc[2*nj+1], aH, bH[1], bH[3]);
                mma_bf16(oacc[2*nj],   aH, bL[0], bL[2]);
                mma_bf16(oacc[2*nj+1], aH, bL[1], bL[3]);
                mma_bf16(oacc[2*nj],   aL, bH[0], bH[2]);
                mma_bf16(oacc[2*nj+1], aL, bH[1], bH[3]);
            }
        }
        __syncthreads();
    }

    // ---- normalize + write O as split bf16 into [b, t, h*64+d] ----
    const int b = bh >> 4, h = bh & 15;
    float inv0 = 1.f / lrow[0], inv1 = 1.f / lrow[1];
    #pragma unroll
    for (int ni = 0; ni < 8; ni++) {
        int d = ni * 8 + t4 * 2;
        #pragma unroll
        for (int half = 0; half < 2; half++) {
            int trow = m0 + wid * 16 + g + half * 8;
            float inv = half ? inv1 : inv0;
            size_t base = ((size_t)b * TT + trow) * CC + h * HD + d;
            uint32_t lw;
            uint32_t hw = pack_split(oacc[ni][half*2+0] * inv,
                                     oacc[ni][half*2+1] * inv, lw);
            *(uint32_t*)(oh + base) = hw;
            *(uint32_t*)(ol + base) = lw;
        }
    }
}

// ---------------- block reductions ----------------
__device__ __forceinline__ float blockReduceSum256(float v, float* sh) {
    #pragma unroll
    for (int o = 16; o > 0; o >>= 1) v += __shfl_xor_sync(0xffffffffu, v, o);
    int w = threadIdx.x >> 5;
    if ((threadIdx.x & 31) == 0) sh[w] = v;
    __syncthreads();
    if (threadIdx.x < 8) {
        v = sh[threadIdx.x];
        #pragma unroll
        for (int o = 4; o > 0; o >>= 1) v += __shfl_xor_sync(0xffu, v, o);
        if (threadIdx.x == 0) sh[0] = v;
    }
    __syncthreads();
    float r = sh[0]; __syncthreads(); return r;
}

__device__ __forceinline__ void split_store(bf16* H, bf16* L, size_t i, float v) {
    bf16 h = __float2bfloat16(v);
    H[i] = h;
    L[i] = __float2bfloat16(v - __bfloat162float(h));
}

// ---------------- layernorm -> split bf16 ----------------
__global__ __launch_bounds__(256)
void layernorm_split_k(const float* __restrict__ x, const float* __restrict__ g,
                       const float* __restrict__ b, bf16* __restrict__ oh, bf16* __restrict__ ol)
{
    __shared__ float sh[8];
    const size_t row = blockIdx.x;
    const float* xr = x + row * CC;
    const int c = threadIdx.x * 4;
    float4 xv = *(const float4*)(xr + c);
    float s  = xv.x + xv.y + xv.z + xv.w;
    float ss = xv.x*xv.x + xv.y*xv.y + xv.z*xv.z + xv.w*xv.w;
    s = blockReduceSum256(s, sh);
    ss = blockReduceSum256(ss, sh);
    float mean = s * (1.f / CC);
    float var = ss * (1.f / CC) - mean * mean;
    float inv = rsqrtf(var + 1e-5f);
    float4 gv = *(const float4*)(g + c);
    float4 bv = *(const float4*)(b + c);
    size_t base = row * CC + c;
    split_store(oh, ol, base + 0, (xv.x - mean) * inv * gv.x + bv.x);
    split_store(oh, ol, base + 1, (xv.y - mean) * inv * gv.y + bv.y);
    split_store(oh, ol, base + 2, (xv.z - mean) * inv * gv.z + bv.z);
    split_store(oh, ol, base + 3, (xv.w - mean) * inv * gv.w + bv.w);
}

// ---------------- weight transpose + split ----------------
__global__ void transpose_split_k(const float* __restrict__ W, bf16* __restrict__ hi,
                                  bf16* __restrict__ lo, int K, int N, long long zOutStride)
{
    __shared__ float t[32][33];
    W  += (size_t)blockIdx.z * K * N;
    hi += (size_t)blockIdx.z * zOutStride;
    lo += (size_t)blockIdx.z * zOutStride;
    int k0 = blockIdx.y * 32, n0 = blockIdx.x * 32;
    int tx = threadIdx.x, ty = threadIdx.y;
    #pragma unroll
    for (int i = 0; i < 32; i += 8)
        t[ty + i][tx] = W[(size_t)(k0 + ty + i) * N + n0 + tx];
    __syncthreads();
    #pragma unroll
    for (int i = 0; i < 32; i += 8)
        split_store(hi, lo, (size_t)(n0 + ty + i) * K + k0 + tx, t[tx][ty + i]);
}

// ---------------- elementwise split ----------------
__global__ void split_k(const float* __restrict__ W, bf16* hi, bf16* lo, int n)
{
    int idx = blockIdx.x * 256 + threadIdx.x;
    if (idx < n) split_store(hi, lo, idx, W[idx]);
}

// ---------------- im2col + split ----------------
__global__ void im2col_split_k(const float* __restrict__ img, bf16* hi, bf16* lo)
{
    int idx = blockIdx.x * 256 + threadIdx.x;
    if (idx >= BB * NPATCH * KIM) return;
    int k = idx % KIM;
    int bn = idx / KIM;
    int n = bn % NPATCH;
    int b = bn / NPATCH;
    int ci = k >> 8;
    int rr = k & 255;
    int kh = rr >> 4;
    int kw = rr & 15;
    int ph = n / 21, pw = n % 21;
    float v = img[(((size_t)b * 3 + ci) * IMG + ph * PATCH + kh) * IMG + pw * PATCH + kw];
    split_store(hi, lo, idx, v);
}

// ---------------- embedding assembly ----------------
__global__ __launch_bounds__(256)
void embed_k(const int* __restrict__ toks, const float* __restrict__ tok_emb,
             const float* __restrict__ txt_pos, const float* __restrict__ img_pos,
             const float* __restrict__ p, float* __restrict__ x)
{
    const int bt = blockIdx.x;
    const int b = bt >> 10;
    const int t = bt & 1023;
    const int c = threadIdx.x * 4;
    const float* src;
    const float* extra = nullptr;
    if (t == 0)      src = tok_emb + 1 * CC;
    else if (t == 1) src = tok_emb + 8 * CC;
    else if (t < 443) {
        int n = t - 2;
        src = p + ((size_t)(b * NPATCH + n)) * CC;
        extra = img_pos + (size_t)n * CC;
    }
    else if (t == 443) src = tok_emb + 9 * CC;
    else {
        int tok = toks[b * TTXT + (t - 444)];
        src = tok_emb + (size_t)tok * CC;
    }
    float4 v = *(const float4*)(src + c);
    float4 tp = *(const float4*)(txt_pos + (size_t)t * CC + c);
    v.x += tp.x; v.y += tp.y; v.z += tp.z; v.w += tp.w;
    if (extra) {
        float4 e = *(const float4*)(extra + c);
        v.x += e.x; v.y += e.y; v.z += e.z; v.w += e.w;
    }
    *(float4*)(x + (size_t)bt * CC + c) = v;
}

// ---------------- host-side GEMM launcher ----------------
static inline void tc(const bf16* Ah, const bf16* Al, const bf16* Bh, const bf16* Bl,
                      const float* bias, const float* res,
                      float* outF, bf16* outH, bf16* outL,
                      int M, int N, int K, int ldc,
                      float alpha = 1.f, int relu = 0, int outMode = 0,
                      bf16* okh = nullptr, bf16* okl = nullptr,
                      bf16* ovh = nullptr, bf16* ovl = nullptr)
{
    dim3 grid((N + 127) / 128, (M + 127) / 128, 1);
    size_t sh = (size_t)(4 * 128 * LDS + 4 * 128 * LDS) * 2;
    gemm_mma<<<grid, 256, sh>>>(Ah, Al, Bh, Bl, bias, res, outF, outH, outL,
        okh, okl, ovh, ovl, M, N, K, ldc, alpha, relu, outMode);
}

#define SYM(name) ({ void* _p; cudaGetSymbolAddress(&_p, name); _p; })

extern "C" void kernel_launch(void* const* d_in, const int* in_sizes, int n_in,
                              void* d_out, int out_size)
{
    const int*   text_tokens = (const int*)  d_in[0];
    const float* images      = (const float*)d_in[1];
    const float* tok_emb     = (const float*)d_in[2];
    const float* txt_pos     = (const float*)d_in[3];
    const float* img_pos     = (const float*)d_in[4];
    const float* patch_w     = (const float*)d_in[5];
    const float* patch_b     = (const float*)d_in[6];
    const float* ln1_g       = (const float*)d_in[7];
    const float* ln1_b       = (const float*)d_in[8];
    const float* wq          = (const float*)d_in[9];
    const float* wk          = (const float*)d_in[10];
    const float* wv          = (const float*)d_in[11];
    const float* wo          = (const float*)d_in[12];
    const float* bo          = (const float*)d_in[13];
    const float* ln2_g       = (const float*)d_in[14];
    const float* ln2_b       = (const float*)d_in[15];
    const float* w1          = (const float*)d_in[16];
    const float* b1          = (const float*)d_in[17];
    const float* w2          = (const float*)d_in[18];
    const float* b2          = (const float*)d_in[19];
    const float* lnf_g       = (const float*)d_in[20];
    const float* lnf_b       = (const float*)d_in[21];
    const float* lm_w        = (const float*)d_in[22];
    const float* lm_b        = (const float*)d_in[23];
    float* out = (float*)d_out;

    cudaFuncSetAttribute(gemm_mma, cudaFuncAttributeMaxDynamicSharedMemorySize,
                         (4 * 128 * LDS + 4 * 128 * LDS) * 2);
    const int FLASH_SMEM = (2 * 128 * LDF + 2 * 4 * 64 * LDF) * 2;
    cudaFuncSetAttribute(flash_attn_k, cudaFuncAttributeMaxDynamicSharedMemorySize,
                         FLASH_SMEM);

    float* px   = (float*)SYM(g_x);
    float* ppp  = (float*)SYM(g_pp);
    bf16 *pqh = (bf16*)SYM(g_qh), *pql = (bf16*)SYM(g_ql);
    bf16 *pkh = (bf16*)SYM(g_kh), *pkl = (bf16*)SYM(g_kl);
    bf16 *pvth = (bf16*)SYM(g_vth), *pvtl = (bf16*)SYM(g_vtl);
    bf16 *pah = (bf16*)SYM(g_ah), *pal = (bf16*)SYM(g_al);
    bf16 *pfh = (bf16*)SYM(g_fh), *pfl = (bf16*)SYM(g_fl);
    bf16 *pwqkvh = (bf16*)SYM(g_wqkvh), *pwqkvl = (bf16*)SYM(g_wqkvl);
    bf16 *pwoh = (bf16*)SYM(g_woh), *pwol = (bf16*)SYM(g_wol);
    bf16 *pw1h = (bf16*)SYM(g_w1h), *pw1l = (bf16*)SYM(g_w1l);
    bf16 *pw2h = (bf16*)SYM(g_w2h), *pw2l = (bf16*)SYM(g_w2l);
    bf16 *plmh = (bf16*)SYM(g_lmh), *plml = (bf16*)SYM(g_lml);
    bf16 *ppwh = (bf16*)SYM(g_pwh), *ppwl = (bf16*)SYM(g_pwl);
    bf16 *pimh = (bf16*)SYM(g_imh), *piml = (bf16*)SYM(g_iml);

    // ---- weight prep: transpose + split (q,k,v fused into [3C, C] per layer) ----
    dim3 tb(32, 8);
    const long long QKV_Z = (long long)3 * CC * CC;
    transpose_split_k<<<dim3(CC/32,  CC/32,  LL), tb>>>(wq, pwqkvh,            pwqkvl,            CC, CC, QKV_Z);
    transpose_split_k<<<dim3(CC/32,  CC/32,  LL), tb>>>(wk, pwqkvh + CC*CC,    pwqkvl + CC*CC,    CC, CC, QKV_Z);
    transpose_split_k<<<dim3(CC/32,  CC/32,  LL), tb>>>(wv, pwqkvh + 2*CC*CC,  pwqkvl + 2*CC*CC,  CC, CC, QKV_Z);
    transpose_split_k<<<dim3(CC/32,  CC/32,  LL), tb>>>(wo, pwoh, pwol, CC, CC, (long long)CC*CC);
    transpose_split_k<<<dim3(FF_/32, CC/32,  LL), tb>>>(w1, pw1h, pw1l, CC, FF_, (long long)CC*FF_);
    transpose_split_k<<<dim3(CC/32,  FF_/32, LL), tb>>>(w2, pw2h, pw2l, FF_, CC, (long long)CC*FF_);
    transpose_split_k<<<dim3(VV/32,  CC/32,  1),  tb>>>(lm_w, plmh, plml, CC, VV, 0);
    split_k<<<(CC*KIM + 255)/256, 256>>>(patch_w, ppwh, ppwl, CC*KIM);

    // ---- patch embedding ----
    im2col_split_k<<<(BB*NPATCH*KIM + 255)/256, 256>>>(images, pimh, piml);
    tc(pimh, piml, ppwh, ppwl, patch_b, nullptr, ppp, nullptr, nullptr,
       BB*NPATCH, CC, KIM, CC);

    // ---- embedding assembly ----
    embed_k<<<BB*TT, 256>>>(text_tokens, tok_emb, txt_pos, img_pos, ppp, px);

    const int M = MTOK;
    for (int l = 0; l < LL; l++) {
        size_t wOff = (size_t)l * CC * CC, w1Off = (size_t)l * CC * FF_;
        size_t qkvOff = (size_t)l * 3 * CC * CC;

        layernorm_split_k<<<M, 256>>>(px, ln1_g + l*CC, ln1_b + l*CC, pah, pal);

        // fused q|k|v projection with direct split scatter (q,k at [b,h,t,d]; vt at [b,h,d,t])
        tc(pah, pal, pwqkvh + qkvOff, pwqkvl + qkvOff, nullptr, nullptr,
           nullptr, pqh, pql, M, 3*CC, CC, 0, 1.f, 0, /*outMode*/1,
           pkh, pkl, pvth, pvtl);

        // fused flash attention -> split bf16 at [b,t,h,d]
        flash_attn_k<<<BB*HH*8, 256, FLASH_SMEM>>>(
            pqh, pql, pkh, pkl, pvth, pvtl, pah, pal);

        // out proj + bias + residual -> x
        tc(pah, pal, pwoh + wOff, pwol + wOff, bo + l*CC, px, px, nullptr, nullptr,
           M, CC, CC, CC);

        layernorm_split_k<<<M, 256>>>(px, ln2_g + l*CC, ln2_b + l*CC, pah, pal);

        // ffn
        tc(pah, pal, pw1h + w1Off, pw1l + w1Off, b1 + l*FF_, nullptr,
           nullptr, pfh, pfl, M, FF_, CC, FF_, 1.f, /*relu*/1);
        tc(pfh, pfl, pw2h + w1Off, pw2l + w1Off, b2 + l*CC, px, px, nullptr, nullptr,
           M, CC, FF_, CC);
    }

    // ---- final LN + LM head ----
    layernorm_split_k<<<M, 256>>>(px, lnf_g, lnf_b, pah, pal);
    tc(pah, pal, plmh, plml, lm_b, nullptr, out, nullptr, nullptr,
       M, VV, CC, VV);
}